// round 1
// baseline (speedup 1.0000x reference)
#include <cuda_runtime.h>
#include <math.h>
#include <float.h>

// ---------------- problem constants ----------------
#define NPTS  4096
#define DIN   784
#define DHID  256
#define MH    4
#define DHEAD 64
#define KP1   11            // TOP_K + 1
#define SIGMA_C 0.1f
#define DE_C  0.30151134457776363f   // 1/sqrt(11)

// ---------------- device scratch (no allocation allowed) ----------------
__device__ float g_dist[(size_t)NPTS * NPTS];        // 64 MB
__device__ float g_sq[NPTS];
__device__ int   g_idx[NPTS * KP1];                  // edge e -> 11 member nodes
__device__ int   g_deg[NPTS];
__device__ float g_dv[NPTS];
__device__ int   g_roff[NPTS + 1];
__device__ int   g_cursor[NPTS];
__device__ int   g_redge[NPTS * KP1];                // CSR: node i -> edges containing i
__device__ uint4 g_A4[(size_t)NPTS * NPTS / 16];     // 16 MB adjacency byte-mask
__device__ float g_XT[NPTS * DHID];                  // X @ theta
__device__ float g_Xe[NPTS * DHID];
__device__ float g_E[NPTS * DHID];
__device__ float g_nrm[NPTS];
__device__ float g_rho[NPTS];
__device__ float g_rhoe[NPTS];
__device__ float g_P[NPTS * DHID];
__device__ float g_Q[NPTS * DHID];
__device__ float g_sv[NPTS];
__device__ float g_tv[NPTS];
__device__ float g_Enew[NPTS * DHID];
__device__ float g_Xcat[NPTS * DHID];
__device__ float g_scal[8];   // [0]=smax [1]=tmax [2]=rho_max [3]=rhoe_max

// ---------------- utility kernels ----------------
__global__ void k_init() {
    size_t i = (size_t)blockIdx.x * blockDim.x + threadIdx.x;   // 4096*256 = 1,048,576
    g_A4[i] = make_uint4(0u, 0u, 0u, 0u);
    if (i < NPTS) g_deg[i] = 0;
}

__global__ void k_rowsq(const float* __restrict__ X) {
    int row = blockIdx.x * 4 + (threadIdx.x >> 5);
    int lane = threadIdx.x & 31;
    float a = 0.f;
    for (int c = lane; c < DIN; c += 32) { float v = X[(size_t)row * DIN + c]; a += v * v; }
    for (int o = 16; o; o >>= 1) a += __shfl_xor_sync(0xffffffffu, a, o);
    if (lane == 0) g_sq[row] = a;
}

// C = X X^T with epilogue dist = |sq_i + sq_j - 2 c|.  128x128 tile, BK=8, 8x8/thread.
__global__ void k_aat_dist(const float* __restrict__ A) {
    __shared__ float As[8][128];
    __shared__ float Bs[8][128];
    int t = threadIdx.x;                 // 256
    int row0 = blockIdx.y * 128, col0 = blockIdx.x * 128;
    int lr = t >> 1, lq = t & 1;
    int ty = t >> 4, tx = t & 15;
    float acc[8][8];
#pragma unroll
    for (int i = 0; i < 8; i++)
#pragma unroll
        for (int j = 0; j < 8; j++) acc[i][j] = 0.f;

    for (int k0 = 0; k0 < DIN; k0 += 8) {
        float4 av = *(const float4*)&A[(size_t)(row0 + lr) * DIN + k0 + lq * 4];
        float4 bv = *(const float4*)&A[(size_t)(col0 + lr) * DIN + k0 + lq * 4];
        As[lq * 4 + 0][lr] = av.x; As[lq * 4 + 1][lr] = av.y;
        As[lq * 4 + 2][lr] = av.z; As[lq * 4 + 3][lr] = av.w;
        Bs[lq * 4 + 0][lr] = bv.x; Bs[lq * 4 + 1][lr] = bv.y;
        Bs[lq * 4 + 2][lr] = bv.z; Bs[lq * 4 + 3][lr] = bv.w;
        __syncthreads();
#pragma unroll
        for (int kk = 0; kk < 8; kk++) {
            float ar[8], br[8];
#pragma unroll
            for (int i = 0; i < 8; i++) ar[i] = As[kk][ty * 8 + i];
#pragma unroll
            for (int j = 0; j < 8; j++) br[j] = Bs[kk][tx * 8 + j];
#pragma unroll
            for (int i = 0; i < 8; i++)
#pragma unroll
                for (int j = 0; j < 8; j++) acc[i][j] += ar[i] * br[j];
        }
        __syncthreads();
    }
#pragma unroll
    for (int i = 0; i < 8; i++) {
        int gi = row0 + ty * 8 + i;
        float si = g_sq[gi];
#pragma unroll
        for (int j = 0; j < 8; j++) {
            int gj = col0 + tx * 8 + j;
            g_dist[(size_t)gi * NPTS + gj] = fabsf(si + g_sq[gj] - 2.f * acc[i][j]);
        }
    }
}

// per-row 11 smallest (tie-break: lower index, matching jax top_k)
__global__ void k_topk() {
    __shared__ float sv[NPTS];
    __shared__ float rv[256];
    __shared__ int   ri[256];
    int row = blockIdx.x, t = threadIdx.x;
    for (int j = t; j < NPTS; j += 256) sv[j] = g_dist[(size_t)row * NPTS + j];
    __syncthreads();
    for (int it = 0; it < KP1; it++) {
        float bv = FLT_MAX; int bi = 0x7fffffff;
        for (int j = t; j < NPTS; j += 256) {
            float v = sv[j];
            if (v < bv || (v == bv && j < bi)) { bv = v; bi = j; }
        }
        rv[t] = bv; ri[t] = bi;
        __syncthreads();
        for (int s = 128; s > 0; s >>= 1) {
            if (t < s) {
                if (rv[t + s] < rv[t] || (rv[t + s] == rv[t] && ri[t + s] < ri[t])) {
                    rv[t] = rv[t + s]; ri[t] = ri[t + s];
                }
            }
            __syncthreads();
        }
        if (t == 0) { g_idx[row * KP1 + it] = ri[0]; sv[ri[0]] = FLT_MAX; }
        __syncthreads();
    }
}

__global__ void k_deg() {
    int i = blockIdx.x * blockDim.x + threadIdx.x;
    if (i < NPTS * KP1) atomicAdd(&g_deg[g_idx[i]], 1);
}

__global__ void k_scan() {
    int t = threadIdx.x;
    for (int i = t; i < NPTS; i += 1024) g_dv[i] = rsqrtf((float)g_deg[i]);
    __syncthreads();
    if (t == 0) {
        int acc = 0;
        for (int i = 0; i < NPTS; i++) { g_roff[i] = acc; acc += g_deg[i]; }
        g_roff[NPTS] = acc;
    }
    __syncthreads();
    for (int i = t; i < NPTS; i += 1024) g_cursor[i] = g_roff[i];
}

__global__ void k_fill() {
    int e = blockIdx.x, t = threadIdx.x;   // 128 threads
    if (t < KP1) {
        int i = g_idx[e * KP1 + t];
        int p = atomicAdd(&g_cursor[i], 1);
        g_redge[p] = e;
    }
    if (t < KP1 * KP1) {
        int a = g_idx[e * KP1 + t / KP1];
        int b = g_idx[e * KP1 + t % KP1];
        ((unsigned char*)g_A4)[(size_t)a * NPTS + b] = 1;
    }
}

// generic row-major GEMM: C[M,Np] = A[M,K] @ B[K,Np]; 64x64 tile, BK=16, 4x4/thread
__global__ void k_gemm(const float* __restrict__ A, const float* __restrict__ B,
                       float* __restrict__ C, int M, int Np, int K, int ldc, int coff) {
    __shared__ float As[16][64];
    __shared__ float Bs[16][64];
    int t = threadIdx.x, tx = t & 15, ty = t >> 4;
    int m0 = blockIdx.y * 64, n0 = blockIdx.x * 64;
    int ar = t >> 2, aq = t & 3;         // A loader: row ar, k-quad aq
    int bkr = t >> 4, bcg = t & 15;      // B loader: k-row bkr, col-quad bcg
    float acc[4][4] = {};
    for (int k0 = 0; k0 < K; k0 += 16) {
        float4 av = *(const float4*)&A[(size_t)(m0 + ar) * K + k0 + aq * 4];
        As[aq * 4 + 0][ar] = av.x; As[aq * 4 + 1][ar] = av.y;
        As[aq * 4 + 2][ar] = av.z; As[aq * 4 + 3][ar] = av.w;
        float4 bv = *(const float4*)&B[(size_t)(k0 + bkr) * Np + n0 + bcg * 4];
        Bs[bkr][bcg * 4 + 0] = bv.x; Bs[bkr][bcg * 4 + 1] = bv.y;
        Bs[bkr][bcg * 4 + 2] = bv.z; Bs[bkr][bcg * 4 + 3] = bv.w;
        __syncthreads();
#pragma unroll
        for (int kk = 0; kk < 16; kk++) {
            float a0 = As[kk][ty * 4 + 0], a1 = As[kk][ty * 4 + 1];
            float a2 = As[kk][ty * 4 + 2], a3 = As[kk][ty * 4 + 3];
            float b0 = Bs[kk][tx * 4 + 0], b1 = Bs[kk][tx * 4 + 1];
            float b2 = Bs[kk][tx * 4 + 2], b3 = Bs[kk][tx * 4 + 3];
            acc[0][0] += a0 * b0; acc[0][1] += a0 * b1; acc[0][2] += a0 * b2; acc[0][3] += a0 * b3;
            acc[1][0] += a1 * b0; acc[1][1] += a1 * b1; acc[1][2] += a1 * b2; acc[1][3] += a1 * b3;
            acc[2][0] += a2 * b0; acc[2][1] += a2 * b1; acc[2][2] += a2 * b2; acc[2][3] += a2 * b3;
            acc[3][0] += a3 * b0; acc[3][1] += a3 * b1; acc[3][2] += a3 * b2; acc[3][3] += a3 * b3;
        }
        __syncthreads();
    }
#pragma unroll
    for (int i = 0; i < 4; i++)
#pragma unroll
        for (int j = 0; j < 4; j++)
            C[(size_t)(m0 + ty * 4 + i) * ldc + coff + n0 + tx * 4 + j] = acc[i][j];
}

// Xe[e] = de * sum_k dv[m_k] * XT[m_k]      (warp per edge, 256 dims)
__global__ void k_gather_edges() {
    int e = blockIdx.x * 4 + (threadIdx.x >> 5);
    int lane = threadIdx.x & 31;
    float acc[8] = {};
    for (int k = 0; k < KP1; k++) {
        int i = g_idx[e * KP1 + k];
        float w = g_dv[i];
        const float* r = &g_XT[(size_t)i * DHID];
#pragma unroll
        for (int j = 0; j < 8; j++) acc[j] += w * r[lane + j * 32];
    }
#pragma unroll
    for (int j = 0; j < 8; j++) g_Xe[(size_t)e * DHID + lane + j * 32] = DE_C * acc[j];
}

// E[i] = dv[i] * de * sum_{e in row(i)} Xe[e]
__global__ void k_gather_nodes() {
    int i = blockIdx.x * 4 + (threadIdx.x >> 5);
    int lane = threadIdx.x & 31;
    int beg = g_roff[i], end = g_roff[i + 1];
    float acc[8] = {};
    for (int k = beg; k < end; k++) {
        const float* r = &g_Xe[(size_t)g_redge[k] * DHID];
#pragma unroll
        for (int j = 0; j < 8; j++) acc[j] += r[lane + j * 32];
    }
    float s = g_dv[i] * DE_C;
#pragma unroll
    for (int j = 0; j < 8; j++) g_E[(size_t)i * DHID + lane + j * 32] = s * acc[j];
}

__global__ void k_rownorm(const float* __restrict__ Xf, float* __restrict__ nrm) {
    int row = blockIdx.x * 4 + (threadIdx.x >> 5);
    int lane = threadIdx.x & 31;
    float a = 0.f;
    for (int c = lane; c < DHID; c += 32) { float v = Xf[(size_t)row * DHID + c]; a += v * v; }
    for (int o = 16; o; o >>= 1) a += __shfl_xor_sync(0xffffffffu, a, o);
    if (lane == 0) nrm[row] = sqrtf(a);
}

// rho[i] = sum_{j adj(i), j!=i} cos_ij if cos_ij > sigma
__global__ void k_density(const float* __restrict__ Xf, const float* __restrict__ nrm) {
    __shared__ float xs[DHID];
    __shared__ int list[NPTS];
    __shared__ int cnt;
    __shared__ float accs;
    int i = blockIdx.x, t = threadIdx.x;   // 256 threads
    if (t == 0) { cnt = 0; accs = 0.f; }
    xs[t] = Xf[(size_t)i * DHID + t];
    __syncthreads();
    const unsigned char* Ab = (const unsigned char*)g_A4;
    for (int j = t; j < NPTS; j += 256)
        if (Ab[(size_t)i * NPTS + j] && j != i) { int p = atomicAdd(&cnt, 1); list[p] = j; }
    __syncthreads();
    int n = cnt, warp = t >> 5, lane = t & 31;
    float part = 0.f;
    float ni = nrm[i];
    for (int e = warp; e < n; e += 8) {
        int j = list[e];
        float dot = 0.f;
        const float* r = &Xf[(size_t)j * DHID];
        for (int c = lane; c < DHID; c += 32) dot += xs[c] * r[c];
        for (int o = 16; o; o >>= 1) dot += __shfl_xor_sync(0xffffffffu, dot, o);
        if (lane == 0) {
            float cs = dot / (ni * nrm[j]);
            if (cs > SIGMA_C) part += cs;
        }
    }
    if (lane == 0) atomicAdd(&accs, part);
    __syncthreads();
    if (t == 0) g_rho[i] = accs;
}

__global__ void k_rhoe() {
    int e = blockIdx.x * blockDim.x + threadIdx.x;
    if (e < NPTS) {
        float r = 0.f;
        for (int k = 0; k < KP1; k++) r += g_rho[g_idx[e * KP1 + k]];
        g_rhoe[e] = r;
    }
}

__global__ void k_max(const float* __restrict__ v, float* __restrict__ o) {
    __shared__ float sm[1024];
    int t = threadIdx.x;
    float m = -FLT_MAX;
    for (int i = t; i < NPTS; i += 1024) m = fmaxf(m, v[i]);
    sm[t] = m;
    __syncthreads();
    for (int s = 512; s > 0; s >>= 1) { if (t < s) sm[t] = fmaxf(sm[t], sm[t + s]); __syncthreads(); }
    if (t == 0) *o = sm[0];
}

template <int D>
__global__ void k_matvec(const float* __restrict__ P, const float* __restrict__ a,
                         float* __restrict__ s) {
    int row = blockIdx.x * 4 + (threadIdx.x >> 5);
    int lane = threadIdx.x & 31;
    float p = 0.f;
    for (int c = lane; c < D; c += 32) p += P[(size_t)row * D + c] * a[c];
    for (int o = 16; o; o >>= 1) p += __shfl_xor_sync(0xffffffffu, p, o);
    if (lane == 0) s[row] = p;
}

__device__ __forceinline__ float lrelu(float x) { return x > 0.f ? x : 0.2f * x; }

// masked softmax attention over CSR rows + elu(att @ val)
template <int D>
__global__ void k_att(const float* __restrict__ s, const float* __restrict__ t,
                      const float* __restrict__ rho,
                      const float* pSmax, const float* pTmax, const float* pRmax,
                      const float* __restrict__ val,
                      float* __restrict__ out, int ldo) {
    int row = blockIdx.x * 4 + (threadIdx.x >> 5);
    int lane = threadIdx.x & 31;
    float ax_max = lrelu(*pSmax + *pTmax);
    float rt = rho[row] / (*pRmax) * ax_max;
    float si = s[row];
    int beg = g_roff[row], end = g_roff[row + 1];
    float m = -FLT_MAX;
    for (int k = beg + lane; k < end; k += 32)
        m = fmaxf(m, lrelu(si + t[g_redge[k]]) + rt);
    for (int o = 16; o; o >>= 1) m = fmaxf(m, __shfl_xor_sync(0xffffffffu, m, o));
    float Z = 0.f;
    for (int k = beg + lane; k < end; k += 32)
        Z += expf(lrelu(si + t[g_redge[k]]) + rt - m);
    for (int o = 16; o; o >>= 1) Z += __shfl_xor_sync(0xffffffffu, Z, o);
    const int CH = D / 32;
    float acc[CH];
#pragma unroll
    for (int j = 0; j < CH; j++) acc[j] = 0.f;
    for (int k = beg; k < end; k++) {
        int e = g_redge[k];
        float w = expf(lrelu(si + t[e]) + rt - m);
        const float* v = &val[(size_t)e * D];
#pragma unroll
        for (int j = 0; j < CH; j++) acc[j] += w * v[lane + j * 32];
    }
    float iz = 1.f / Z;
#pragma unroll
    for (int j = 0; j < CH; j++) {
        float x = acc[j] * iz;
        out[(size_t)row * ldo + lane + j * 32] = x > 0.f ? x : expm1f(x);
    }
}

// ---------------- host orchestration ----------------
template <typename T>
static T* symaddr(T& sym) { void* p = nullptr; cudaGetSymbolAddress(&p, sym); return (T*)p; }

extern "C" void kernel_launch(void* const* d_in, const int* in_sizes, int n_in,
                              void* d_out, int out_size) {
    const float* X     = (const float*)d_in[0];  // [4096,784]
    const float* theta = (const float*)d_in[1];  // [784,256]
    const float* Wh    = (const float*)d_in[2];  // [4,256,64]
    const float* axh   = (const float*)d_in[3];  // [4,128,1]
    const float* aeh   = (const float*)d_in[4];  // [4,128,1]
    const float* W2    = (const float*)d_in[5];  // [256,256]
    const float* ax2   = (const float*)d_in[6];  // [512,1]
    const float* ae2   = (const float*)d_in[7];  // [512,1]
    float* out = (float*)d_out;

    float* pXT   = symaddr(*g_XT)   ? (float*)nullptr : nullptr; // placeholder (unused path)
    // fetch symbol addresses (pure queries — capture-safe)
    void* vp;
    cudaGetSymbolAddress(&vp, g_XT);   float* XT   = (float*)vp;
    cudaGetSymbolAddress(&vp, g_Xe);   float* Xe   = (float*)vp;
    cudaGetSymbolAddress(&vp, g_E);    float* E    = (float*)vp;
    cudaGetSymbolAddress(&vp, g_nrm);  float* nrm  = (float*)vp;
    cudaGetSymbolAddress(&vp, g_rho);  float* rho  = (float*)vp;
    cudaGetSymbolAddress(&vp, g_rhoe); float* rhoe = (float*)vp;
    cudaGetSymbolAddress(&vp, g_P);    float* P    = (float*)vp;
    cudaGetSymbolAddress(&vp, g_Q);    float* Q    = (float*)vp;
    cudaGetSymbolAddress(&vp, g_sv);   float* sv   = (float*)vp;
    cudaGetSymbolAddress(&vp, g_tv);   float* tv   = (float*)vp;
    cudaGetSymbolAddress(&vp, g_Enew); float* Enew = (float*)vp;
    cudaGetSymbolAddress(&vp, g_Xcat); float* Xcat = (float*)vp;
    cudaGetSymbolAddress(&vp, g_scal); float* scal = (float*)vp;
    (void)pXT; (void)in_sizes; (void)n_in; (void)out_size;

    // ---- HGCN ----
    k_init<<<4096, 256>>>();
    k_rowsq<<<NPTS / 4, 128>>>(X);
    k_aat_dist<<<dim3(NPTS / 128, NPTS / 128), 256>>>(X);
    k_topk<<<NPTS, 256>>>();
    k_deg<<<(NPTS * KP1 + 255) / 256, 256>>>();
    k_scan<<<1, 1024>>>();
    k_fill<<<NPTS, 128>>>();
    k_gemm<<<dim3(DHID / 64, NPTS / 64), 256>>>(X, theta, XT, NPTS, DHID, DIN, DHID, 0);
    k_gather_edges<<<NPTS / 4, 128>>>();
    k_gather_nodes<<<NPTS / 4, 128>>>();

    // ---- densities (head-independent, stage 1) ----
    k_rownorm<<<NPTS / 4, 128>>>(Xe, nrm);
    k_density<<<NPTS, 256>>>(Xe, nrm);
    k_rhoe<<<NPTS / 256, 256>>>();
    k_max<<<1, 1024>>>(rho, scal + 2);
    k_max<<<1, 1024>>>(rhoe, scal + 3);

    // ---- 4 attention heads ----
    for (int h = 0; h < MH; h++) {
        const float* W  = Wh  + (size_t)h * DHID * DHEAD;
        const float* ax = axh + (size_t)h * 2 * DHEAD;
        const float* ae = aeh + (size_t)h * 2 * DHEAD;
        k_gemm<<<dim3(1, NPTS / 64), 256>>>(Xe, W, P, NPTS, DHEAD, DHID, DHEAD, 0);
        k_gemm<<<dim3(1, NPTS / 64), 256>>>(E,  W, Q, NPTS, DHEAD, DHID, DHEAD, 0);
        // attention 1: nodes attend over edges; val = P
        k_matvec<DHEAD><<<NPTS / 4, 128>>>(P, ax, sv);
        k_matvec<DHEAD><<<NPTS / 4, 128>>>(Q, ax + DHEAD, tv);
        k_max<<<1, 1024>>>(sv, scal + 0);
        k_max<<<1, 1024>>>(tv, scal + 1);
        k_att<DHEAD><<<NPTS / 4, 128>>>(sv, tv, rho, scal + 0, scal + 1, scal + 2,
                                        P, Enew, DHEAD);
        // attention 2: edges attend over nodes; val = Enew (no proj)
        k_matvec<DHEAD><<<NPTS / 4, 128>>>(Q, ae, sv);
        k_matvec<DHEAD><<<NPTS / 4, 128>>>(P, ae + DHEAD, tv);
        k_max<<<1, 1024>>>(sv, scal + 0);
        k_max<<<1, 1024>>>(tv, scal + 1);
        k_att<DHEAD><<<NPTS / 4, 128>>>(sv, tv, rhoe, scal + 0, scal + 1, scal + 3,
                                        Enew, Xcat + h * DHEAD, DHID);
    }

    // ---- final DA-HGAN layer (d = 256) ----
    k_rownorm<<<NPTS / 4, 128>>>(Xcat, nrm);
    k_density<<<NPTS, 256>>>(Xcat, nrm);
    k_rhoe<<<NPTS / 256, 256>>>();
    k_max<<<1, 1024>>>(rho, scal + 2);
    k_max<<<1, 1024>>>(rhoe, scal + 3);

    k_gemm<<<dim3(DHID / 64, NPTS / 64), 256>>>(Xcat, W2, P, NPTS, DHID, DHID, DHID, 0);
    k_gemm<<<dim3(DHID / 64, NPTS / 64), 256>>>(E,    W2, Q, NPTS, DHID, DHID, DHID, 0);

    k_matvec<DHID><<<NPTS / 4, 128>>>(P, ax2, sv);
    k_matvec<DHID><<<NPTS / 4, 128>>>(Q, ax2 + DHID, tv);
    k_max<<<1, 1024>>>(sv, scal + 0);
    k_max<<<1, 1024>>>(tv, scal + 1);
    k_att<DHID><<<NPTS / 4, 128>>>(sv, tv, rho, scal + 0, scal + 1, scal + 2,
                                   P, Enew, DHID);

    k_matvec<DHID><<<NPTS / 4, 128>>>(Q, ae2, sv);
    k_matvec<DHID><<<NPTS / 4, 128>>>(P, ae2 + DHID, tv);
    k_max<<<1, 1024>>>(sv, scal + 0);
    k_max<<<1, 1024>>>(tv, scal + 1);
    k_att<DHID><<<NPTS / 4, 128>>>(sv, tv, rhoe, scal + 0, scal + 1, scal + 3,
                                   Enew, out, DHID);
}

// round 2
// speedup vs baseline: 1.0990x; 1.0990x over previous
#include <cuda_runtime.h>
#include <math.h>
#include <float.h>

// ---------------- problem constants ----------------
#define NPTS  4096
#define DIN   784
#define DHID  256
#define MH    4
#define DHEAD 64
#define KP1   11            // TOP_K + 1
#define SIGMA_C 0.1f
#define DE_C  0.30151134457776363f   // 1/sqrt(11)

// ---------------- device scratch ----------------
__device__ float g_dist[(size_t)NPTS * NPTS];        // 64 MB
__device__ float g_sq[NPTS];
__device__ int   g_idx[NPTS * KP1];                  // edge e -> 11 member nodes
__device__ int   g_deg[NPTS];
__device__ float g_dv[NPTS];
__device__ int   g_roff[NPTS + 1];
__device__ int   g_cursor[NPTS];
__device__ int   g_redge[NPTS * KP1];                // CSR: node i -> edges containing i
__device__ uint4 g_A4[(size_t)NPTS * NPTS / 16];     // 16 MB adjacency byte-mask
__device__ float g_XT[NPTS * DHID];
__device__ float g_Xe[NPTS * DHID];
__device__ float g_E[NPTS * DHID];
__device__ float g_nrm[NPTS];
__device__ float g_rho[NPTS];
__device__ float g_rhoe[NPTS];
__device__ float g_P[NPTS * DHID];
__device__ float g_Q[NPTS * DHID];
__device__ float g_sv[NPTS];
__device__ float g_tv[NPTS];
__device__ float g_Enew[NPTS * DHID];
__device__ float g_Xcat[NPTS * DHID];
__device__ float g_scal[8];   // [0]=smax [1]=tmax [2]=rho_max [3]=rhoe_max

// ---------------- small kernels ----------------
__global__ void k_init() {
    size_t i = (size_t)blockIdx.x * blockDim.x + threadIdx.x;
    g_A4[i] = make_uint4(0u, 0u, 0u, 0u);
    if (i < NPTS) g_deg[i] = 0;
}

__global__ void k_rowsq(const float* __restrict__ X) {
    int row = blockIdx.x * 4 + (threadIdx.x >> 5);
    int lane = threadIdx.x & 31;
    float a = 0.f;
    for (int c = lane; c < DIN; c += 32) { float v = X[(size_t)row * DIN + c]; a += v * v; }
    for (int o = 16; o; o >>= 1) a += __shfl_xor_sync(0xffffffffu, a, o);
    if (lane == 0) g_sq[row] = a;
}

// ---- symmetric dist GEMM: only upper-tri 128x128 blocks, mirrored f4 writes ----
__global__ void k_aat_dist_sym(const float* __restrict__ A) {
    __shared__ float As[2][16][128];
    __shared__ float Bs[2][16][128];
    int b = blockIdx.x, by = 0;
    while (b >= 32 - by) { b -= 32 - by; ++by; }
    int bx = by + b;
    int row0 = by * 128, col0 = bx * 128;
    int t = threadIdx.x;
    int ty = t >> 4, tx = t & 15;
    int ra = t >> 2, qa = (t & 3) * 4;     // loads rows ra, ra+64, k cols qa..qa+3

    float4 pa0, pa1, pb0, pb1;
    pa0 = *(const float4*)&A[(size_t)(row0 + ra) * DIN + qa];
    pa1 = *(const float4*)&A[(size_t)(row0 + ra + 64) * DIN + qa];
    pb0 = *(const float4*)&A[(size_t)(col0 + ra) * DIN + qa];
    pb1 = *(const float4*)&A[(size_t)(col0 + ra + 64) * DIN + qa];
    As[0][qa + 0][ra] = pa0.x; As[0][qa + 1][ra] = pa0.y; As[0][qa + 2][ra] = pa0.z; As[0][qa + 3][ra] = pa0.w;
    As[0][qa + 0][ra + 64] = pa1.x; As[0][qa + 1][ra + 64] = pa1.y; As[0][qa + 2][ra + 64] = pa1.z; As[0][qa + 3][ra + 64] = pa1.w;
    Bs[0][qa + 0][ra] = pb0.x; Bs[0][qa + 1][ra] = pb0.y; Bs[0][qa + 2][ra] = pb0.z; Bs[0][qa + 3][ra] = pb0.w;
    Bs[0][qa + 0][ra + 64] = pb1.x; Bs[0][qa + 1][ra + 64] = pb1.y; Bs[0][qa + 2][ra + 64] = pb1.z; Bs[0][qa + 3][ra + 64] = pb1.w;
    __syncthreads();

    float acc[8][8];
#pragma unroll
    for (int i = 0; i < 8; i++)
#pragma unroll
        for (int j = 0; j < 8; j++) acc[i][j] = 0.f;

    const int nIt = DIN / 16;   // 49
    for (int it = 0; it < nIt; ++it) {
        int k0n = (it + 1) * 16;
        if (it + 1 < nIt) {
            pa0 = *(const float4*)&A[(size_t)(row0 + ra) * DIN + k0n + qa];
            pa1 = *(const float4*)&A[(size_t)(row0 + ra + 64) * DIN + k0n + qa];
            pb0 = *(const float4*)&A[(size_t)(col0 + ra) * DIN + k0n + qa];
            pb1 = *(const float4*)&A[(size_t)(col0 + ra + 64) * DIN + k0n + qa];
        }
        int buf = it & 1;
#pragma unroll
        for (int kk = 0; kk < 16; ++kk) {
            float4 a0 = *(const float4*)&As[buf][kk][ty * 8];
            float4 a1 = *(const float4*)&As[buf][kk][ty * 8 + 4];
            float4 b0 = *(const float4*)&Bs[buf][kk][tx * 8];
            float4 b1 = *(const float4*)&Bs[buf][kk][tx * 8 + 4];
            float ar[8] = {a0.x, a0.y, a0.z, a0.w, a1.x, a1.y, a1.z, a1.w};
            float br[8] = {b0.x, b0.y, b0.z, b0.w, b1.x, b1.y, b1.z, b1.w};
#pragma unroll
            for (int i = 0; i < 8; i++)
#pragma unroll
                for (int j = 0; j < 8; j++) acc[i][j] += ar[i] * br[j];
        }
        if (it + 1 < nIt) {
            int nb = buf ^ 1;
            As[nb][qa + 0][ra] = pa0.x; As[nb][qa + 1][ra] = pa0.y; As[nb][qa + 2][ra] = pa0.z; As[nb][qa + 3][ra] = pa0.w;
            As[nb][qa + 0][ra + 64] = pa1.x; As[nb][qa + 1][ra + 64] = pa1.y; As[nb][qa + 2][ra + 64] = pa1.z; As[nb][qa + 3][ra + 64] = pa1.w;
            Bs[nb][qa + 0][ra] = pb0.x; Bs[nb][qa + 1][ra] = pb0.y; Bs[nb][qa + 2][ra] = pb0.z; Bs[nb][qa + 3][ra] = pb0.w;
            Bs[nb][qa + 0][ra + 64] = pb1.x; Bs[nb][qa + 1][ra + 64] = pb1.y; Bs[nb][qa + 2][ra + 64] = pb1.z; Bs[nb][qa + 3][ra + 64] = pb1.w;
        }
        __syncthreads();
    }

    float si_[8], sj_[8];
#pragma unroll
    for (int i = 0; i < 8; i++) si_[i] = g_sq[row0 + ty * 8 + i];
#pragma unroll
    for (int j = 0; j < 8; j++) sj_[j] = g_sq[col0 + tx * 8 + j];

    // row-major writes (upper block)
#pragma unroll
    for (int i = 0; i < 8; i++) {
        int gi = row0 + ty * 8 + i;
        float4 w0, w1;
        w0.x = fabsf(si_[i] + sj_[0] - 2.f * acc[i][0]);
        w0.y = fabsf(si_[i] + sj_[1] - 2.f * acc[i][1]);
        w0.z = fabsf(si_[i] + sj_[2] - 2.f * acc[i][2]);
        w0.w = fabsf(si_[i] + sj_[3] - 2.f * acc[i][3]);
        w1.x = fabsf(si_[i] + sj_[4] - 2.f * acc[i][4]);
        w1.y = fabsf(si_[i] + sj_[5] - 2.f * acc[i][5]);
        w1.z = fabsf(si_[i] + sj_[6] - 2.f * acc[i][6]);
        w1.w = fabsf(si_[i] + sj_[7] - 2.f * acc[i][7]);
        *(float4*)&g_dist[(size_t)gi * NPTS + col0 + tx * 8] = w0;
        *(float4*)&g_dist[(size_t)gi * NPTS + col0 + tx * 8 + 4] = w1;
    }
    // transposed writes (lower block) — acc[0..7][j] covers 8 consecutive gi
#pragma unroll
    for (int j = 0; j < 8; j++) {
        int gj = col0 + tx * 8 + j;
        float4 w0, w1;
        w0.x = fabsf(si_[0] + sj_[j] - 2.f * acc[0][j]);
        w0.y = fabsf(si_[1] + sj_[j] - 2.f * acc[1][j]);
        w0.z = fabsf(si_[2] + sj_[j] - 2.f * acc[2][j]);
        w0.w = fabsf(si_[3] + sj_[j] - 2.f * acc[3][j]);
        w1.x = fabsf(si_[4] + sj_[j] - 2.f * acc[4][j]);
        w1.y = fabsf(si_[5] + sj_[j] - 2.f * acc[5][j]);
        w1.z = fabsf(si_[6] + sj_[j] - 2.f * acc[6][j]);
        w1.w = fabsf(si_[7] + sj_[j] - 2.f * acc[7][j]);
        *(float4*)&g_dist[(size_t)gj * NPTS + row0 + ty * 8] = w0;
        *(float4*)&g_dist[(size_t)gj * NPTS + row0 + ty * 8 + 4] = w1;
    }
}

// ---- top-11 per row: per-thread sorted list + shfl argmin rounds ----
__device__ __forceinline__ bool pless(float av, int ai, float bv, int bi) {
    return av < bv || (av == bv && ai < bi);
}

__global__ void k_topk() {
    __shared__ float lvS[KP1 * 256];
    __shared__ int   liS[KP1 * 256];
    __shared__ float wv[8];
    __shared__ int   wi[8];
    __shared__ int   sel;
    int row = blockIdx.x, t = threadIdx.x;
    const float* drow = &g_dist[(size_t)row * NPTS];
    float lv[KP1]; int li[KP1];
#pragma unroll
    for (int q = 0; q < KP1; q++) { lv[q] = FLT_MAX; li[q] = 0x7fffffff; }
#pragma unroll
    for (int s = 0; s < 16; s++) {
        int j = t + (s << 8);
        float v = drow[j];
        if (pless(v, j, lv[KP1 - 1], li[KP1 - 1])) {
            lv[KP1 - 1] = v; li[KP1 - 1] = j;
#pragma unroll
            for (int q = KP1 - 1; q > 0; q--) {
                if (pless(lv[q], li[q], lv[q - 1], li[q - 1])) {
                    float tv_ = lv[q]; lv[q] = lv[q - 1]; lv[q - 1] = tv_;
                    int ti_ = li[q]; li[q] = li[q - 1]; li[q - 1] = ti_;
                }
            }
        }
    }
#pragma unroll
    for (int q = 0; q < KP1; q++) { lvS[q * 256 + t] = lv[q]; liS[q * 256 + t] = li[q]; }
    __syncthreads();
    int p = 0;
    for (int it = 0; it < KP1; ++it) {
        float v = (p < KP1) ? lvS[p * 256 + t] : FLT_MAX;
        int ix = (p < KP1) ? liS[p * 256 + t] : 0x7fffffff;
#pragma unroll
        for (int o = 16; o; o >>= 1) {
            float ov = __shfl_xor_sync(0xffffffffu, v, o);
            int oi = __shfl_xor_sync(0xffffffffu, ix, o);
            if (pless(ov, oi, v, ix)) { v = ov; ix = oi; }
        }
        if ((t & 31) == 0) { wv[t >> 5] = v; wi[t >> 5] = ix; }
        __syncthreads();
        if (t < 32) {
            float v2 = t < 8 ? wv[t] : FLT_MAX;
            int i2 = t < 8 ? wi[t] : 0x7fffffff;
#pragma unroll
            for (int o = 4; o; o >>= 1) {
                float ov = __shfl_xor_sync(0xffffffffu, v2, o);
                int oi = __shfl_xor_sync(0xffffffffu, i2, o);
                if (pless(ov, oi, v2, i2)) { v2 = ov; i2 = oi; }
            }
            if (t == 0) { g_idx[row * KP1 + it] = i2; sel = i2; }
        }
        __syncthreads();
        if (p < KP1 && liS[p * 256 + t] == sel) p++;
    }
}

__global__ void k_deg() {
    int i = blockIdx.x * blockDim.x + threadIdx.x;
    if (i < NPTS * KP1) atomicAdd(&g_deg[g_idx[i]], 1);
}

__global__ void k_scan() {
    int t = threadIdx.x;
    for (int i = t; i < NPTS; i += 1024) g_dv[i] = rsqrtf((float)g_deg[i]);
    __syncthreads();
    if (t == 0) {
        int acc = 0;
        for (int i = 0; i < NPTS; i++) { g_roff[i] = acc; acc += g_deg[i]; }
        g_roff[NPTS] = acc;
    }
    __syncthreads();
    for (int i = t; i < NPTS; i += 1024) g_cursor[i] = g_roff[i];
}

__global__ void k_fill() {
    int e = blockIdx.x, t = threadIdx.x;   // 128 threads
    if (t < KP1) {
        int i = g_idx[e * KP1 + t];
        int p = atomicAdd(&g_cursor[i], 1);
        g_redge[p] = e;
    }
    if (t < KP1 * KP1) {
        int a = g_idx[e * KP1 + t / KP1];
        int b = g_idx[e * KP1 + t % KP1];
        ((unsigned char*)g_A4)[(size_t)a * NPTS + b] = 1;
    }
}

// ---- generic 128x128 GEMM, double buffered (Np multiple of 128, K multiple of 16) ----
__global__ void k_gemm128(const float* __restrict__ A, const float* __restrict__ B,
                          float* __restrict__ C, int K, int Np) {
    __shared__ float As[2][16][128];
    __shared__ float Bs[2][16][128];
    int t = threadIdx.x;
    int m0 = blockIdx.y * 128, n0 = blockIdx.x * 128;
    int ty = t >> 4, tx = t & 15;
    int ra = t >> 2, qa = (t & 3) * 4;
    int kb = t >> 5, cb = (t & 31) * 4;

    float4 pa0, pa1, pb0, pb1;
    pa0 = *(const float4*)&A[(size_t)(m0 + ra) * K + qa];
    pa1 = *(const float4*)&A[(size_t)(m0 + ra + 64) * K + qa];
    pb0 = *(const float4*)&B[(size_t)kb * Np + n0 + cb];
    pb1 = *(const float4*)&B[(size_t)(kb + 8) * Np + n0 + cb];
    As[0][qa + 0][ra] = pa0.x; As[0][qa + 1][ra] = pa0.y; As[0][qa + 2][ra] = pa0.z; As[0][qa + 3][ra] = pa0.w;
    As[0][qa + 0][ra + 64] = pa1.x; As[0][qa + 1][ra + 64] = pa1.y; As[0][qa + 2][ra + 64] = pa1.z; As[0][qa + 3][ra + 64] = pa1.w;
    *(float4*)&Bs[0][kb][cb] = pb0;
    *(float4*)&Bs[0][kb + 8][cb] = pb1;
    __syncthreads();

    float acc[8][8];
#pragma unroll
    for (int i = 0; i < 8; i++)
#pragma unroll
        for (int j = 0; j < 8; j++) acc[i][j] = 0.f;

    int nIt = K / 16;
    for (int it = 0; it < nIt; ++it) {
        int k0n = (it + 1) * 16;
        if (it + 1 < nIt) {
            pa0 = *(const float4*)&A[(size_t)(m0 + ra) * K + k0n + qa];
            pa1 = *(const float4*)&A[(size_t)(m0 + ra + 64) * K + k0n + qa];
            pb0 = *(const float4*)&B[(size_t)(k0n + kb) * Np + n0 + cb];
            pb1 = *(const float4*)&B[(size_t)(k0n + kb + 8) * Np + n0 + cb];
        }
        int buf = it & 1;
#pragma unroll
        for (int kk = 0; kk < 16; ++kk) {
            float4 a0 = *(const float4*)&As[buf][kk][ty * 8];
            float4 a1 = *(const float4*)&As[buf][kk][ty * 8 + 4];
            float4 b0 = *(const float4*)&Bs[buf][kk][tx * 8];
            float4 b1 = *(const float4*)&Bs[buf][kk][tx * 8 + 4];
            float ar[8] = {a0.x, a0.y, a0.z, a0.w, a1.x, a1.y, a1.z, a1.w};
            float br[8] = {b0.x, b0.y, b0.z, b0.w, b1.x, b1.y, b1.z, b1.w};
#pragma unroll
            for (int i = 0; i < 8; i++)
#pragma unroll
                for (int j = 0; j < 8; j++) acc[i][j] += ar[i] * br[j];
        }
        if (it + 1 < nIt) {
            int nb = buf ^ 1;
            As[nb][qa + 0][ra] = pa0.x; As[nb][qa + 1][ra] = pa0.y; As[nb][qa + 2][ra] = pa0.z; As[nb][qa + 3][ra] = pa0.w;
            As[nb][qa + 0][ra + 64] = pa1.x; As[nb][qa + 1][ra + 64] = pa1.y; As[nb][qa + 2][ra + 64] = pa1.z; As[nb][qa + 3][ra + 64] = pa1.w;
            *(float4*)&Bs[nb][kb][cb] = pb0;
            *(float4*)&Bs[nb][kb + 8][cb] = pb1;
        }
        __syncthreads();
    }
#pragma unroll
    for (int i = 0; i < 8; i++) {
        int gi = m0 + ty * 8 + i;
        float4 w0 = {acc[i][0], acc[i][1], acc[i][2], acc[i][3]};
        float4 w1 = {acc[i][4], acc[i][5], acc[i][6], acc[i][7]};
        *(float4*)&C[(size_t)gi * Np + n0 + tx * 8] = w0;
        *(float4*)&C[(size_t)gi * Np + n0 + tx * 8 + 4] = w1;
    }
}

// ---- concatenated-heads GEMM: C[4096,256] = A[4096,256] @ Wcat, Wh=[4][256][64] ----
__global__ void k_gemm_heads(const float* __restrict__ A, const float* __restrict__ Wh,
                             float* __restrict__ C) {
    __shared__ float As[2][16][128];
    __shared__ float Bs[2][16][128];
    int t = threadIdx.x;
    int m0 = blockIdx.y * 128, n0 = blockIdx.x * 128;
    int ty = t >> 4, tx = t & 15;
    int ra = t >> 2, qa = (t & 3) * 4;
    int kb = t >> 5, cb = (t & 31) * 4;
    const int K = DHID, Np = DHID;
    int col = n0 + cb;
    int hh = col >> 6, wn = col & 63;
    const float* Bb = Wh + (size_t)hh * DHID * 64 + wn;

    float4 pa0, pa1, pb0, pb1;
    pa0 = *(const float4*)&A[(size_t)(m0 + ra) * K + qa];
    pa1 = *(const float4*)&A[(size_t)(m0 + ra + 64) * K + qa];
    pb0 = *(const float4*)&Bb[(size_t)kb * 64];
    pb1 = *(const float4*)&Bb[(size_t)(kb + 8) * 64];
    As[0][qa + 0][ra] = pa0.x; As[0][qa + 1][ra] = pa0.y; As[0][qa + 2][ra] = pa0.z; As[0][qa + 3][ra] = pa0.w;
    As[0][qa + 0][ra + 64] = pa1.x; As[0][qa + 1][ra + 64] = pa1.y; As[0][qa + 2][ra + 64] = pa1.z; As[0][qa + 3][ra + 64] = pa1.w;
    *(float4*)&Bs[0][kb][cb] = pb0;
    *(float4*)&Bs[0][kb + 8][cb] = pb1;
    __syncthreads();

    float acc[8][8];
#pragma unroll
    for (int i = 0; i < 8; i++)
#pragma unroll
        for (int j = 0; j < 8; j++) acc[i][j] = 0.f;

    const int nIt = K / 16;   // 16
    for (int it = 0; it < nIt; ++it) {
        int k0n = (it + 1) * 16;
        if (it + 1 < nIt) {
            pa0 = *(const float4*)&A[(size_t)(m0 + ra) * K + k0n + qa];
            pa1 = *(const float4*)&A[(size_t)(m0 + ra + 64) * K + k0n + qa];
            pb0 = *(const float4*)&Bb[(size_t)(k0n + kb) * 64];
            pb1 = *(const float4*)&Bb[(size_t)(k0n + kb + 8) * 64];
        }
        int buf = it & 1;
#pragma unroll
        for (int kk = 0; kk < 16; ++kk) {
            float4 a0 = *(const float4*)&As[buf][kk][ty * 8];
            float4 a1 = *(const float4*)&As[buf][kk][ty * 8 + 4];
            float4 b0 = *(const float4*)&Bs[buf][kk][tx * 8];
            float4 b1 = *(const float4*)&Bs[buf][kk][tx * 8 + 4];
            float ar[8] = {a0.x, a0.y, a0.z, a0.w, a1.x, a1.y, a1.z, a1.w};
            float br[8] = {b0.x, b0.y, b0.z, b0.w, b1.x, b1.y, b1.z, b1.w};
#pragma unroll
            for (int i = 0; i < 8; i++)
#pragma unroll
                for (int j = 0; j < 8; j++) acc[i][j] += ar[i] * br[j];
        }
        if (it + 1 < nIt) {
            int nb = buf ^ 1;
            As[nb][qa + 0][ra] = pa0.x; As[nb][qa + 1][ra] = pa0.y; As[nb][qa + 2][ra] = pa0.z; As[nb][qa + 3][ra] = pa0.w;
            As[nb][qa + 0][ra + 64] = pa1.x; As[nb][qa + 1][ra + 64] = pa1.y; As[nb][qa + 2][ra + 64] = pa1.z; As[nb][qa + 3][ra + 64] = pa1.w;
            *(float4*)&Bs[nb][kb][cb] = pb0;
            *(float4*)&Bs[nb][kb + 8][cb] = pb1;
        }
        __syncthreads();
    }
#pragma unroll
    for (int i = 0; i < 8; i++) {
        int gi = m0 + ty * 8 + i;
        float4 w0 = {acc[i][0], acc[i][1], acc[i][2], acc[i][3]};
        float4 w1 = {acc[i][4], acc[i][5], acc[i][6], acc[i][7]};
        *(float4*)&C[(size_t)gi * Np + n0 + tx * 8] = w0;
        *(float4*)&C[(size_t)gi * Np + n0 + tx * 8 + 4] = w1;
    }
}

// ---- hypergraph gathers ----
__global__ void k_gather_edges() {
    int e = blockIdx.x * 4 + (threadIdx.x >> 5);
    int lane = threadIdx.x & 31;
    float acc[8] = {};
    for (int k = 0; k < KP1; k++) {
        int i = g_idx[e * KP1 + k];
        float w = g_dv[i];
        const float* r = &g_XT[(size_t)i * DHID];
#pragma unroll
        for (int j = 0; j < 8; j++) acc[j] += w * r[lane + j * 32];
    }
#pragma unroll
    for (int j = 0; j < 8; j++) g_Xe[(size_t)e * DHID + lane + j * 32] = DE_C * acc[j];
}

__global__ void k_gather_nodes() {
    int i = blockIdx.x * 4 + (threadIdx.x >> 5);
    int lane = threadIdx.x & 31;
    int beg = g_roff[i], end = g_roff[i + 1];
    float acc[8] = {};
    for (int k = beg; k < end; k++) {
        const float* r = &g_Xe[(size_t)g_redge[k] * DHID];
#pragma unroll
        for (int j = 0; j < 8; j++) acc[j] += r[lane + j * 32];
    }
    float s = g_dv[i] * DE_C;
#pragma unroll
    for (int j = 0; j < 8; j++) g_E[(size_t)i * DHID + lane + j * 32] = s * acc[j];
}

__global__ void k_rownorm(const float* __restrict__ Xf, float* __restrict__ nrm) {
    int row = blockIdx.x * 4 + (threadIdx.x >> 5);
    int lane = threadIdx.x & 31;
    float a = 0.f;
    for (int c = lane; c < DHID; c += 32) { float v = Xf[(size_t)row * DHID + c]; a += v * v; }
    for (int o = 16; o; o >>= 1) a += __shfl_xor_sync(0xffffffffu, a, o);
    if (lane == 0) nrm[row] = sqrtf(a);
}

__global__ void k_density(const float* __restrict__ Xf, const float* __restrict__ nrm) {
    __shared__ float xs[DHID];
    __shared__ int list[NPTS];
    __shared__ int cnt;
    __shared__ float accs;
    int i = blockIdx.x, t = threadIdx.x;   // 256 threads
    if (t == 0) { cnt = 0; accs = 0.f; }
    xs[t] = Xf[(size_t)i * DHID + t];
    __syncthreads();
    const unsigned char* Ab = (const unsigned char*)g_A4;
    for (int j = t; j < NPTS; j += 256)
        if (Ab[(size_t)i * NPTS + j] && j != i) { int p = atomicAdd(&cnt, 1); list[p] = j; }
    __syncthreads();
    int n = cnt, warp = t >> 5, lane = t & 31;
    float part = 0.f;
    float ni = nrm[i];
    for (int e = warp; e < n; e += 8) {
        int j = list[e];
        float dot = 0.f;
        const float* r = &Xf[(size_t)j * DHID];
        for (int c = lane; c < DHID; c += 32) dot += xs[c] * r[c];
        for (int o = 16; o; o >>= 1) dot += __shfl_xor_sync(0xffffffffu, dot, o);
        if (lane == 0) {
            float cs = dot / (ni * nrm[j]);
            if (cs > SIGMA_C) part += cs;
        }
    }
    if (lane == 0) atomicAdd(&accs, part);
    __syncthreads();
    if (t == 0) g_rho[i] = accs;
}

__global__ void k_rhoe() {
    int e = blockIdx.x * blockDim.x + threadIdx.x;
    if (e < NPTS) {
        float r = 0.f;
        for (int k = 0; k < KP1; k++) r += g_rho[g_idx[e * KP1 + k]];
        g_rhoe[e] = r;
    }
}

// ---- fused s/t matvec: warp per row, 8192 warps ----
__global__ void k_sv_tv(const float* __restrict__ A1, const float* __restrict__ a1,
                        const float* __restrict__ A2, const float* __restrict__ a2,
                        int ld, int D) {
    int w = (blockIdx.x * blockDim.x + threadIdx.x) >> 5;
    int lane = threadIdx.x & 31;
    const float* A; const float* a; float* o; int row;
    if (w < NPTS) { A = A1; a = a1; o = g_sv; row = w; }
    else { A = A2; a = a2; o = g_tv; row = w - NPTS; }
    float p = 0.f;
    for (int c = lane; c < D; c += 32) p += A[(size_t)row * ld + c] * a[c];
    for (int of = 16; of; of >>= 1) p += __shfl_xor_sync(0xffffffffu, p, of);
    if (lane == 0) o[row] = p;
}

__global__ void k_max2(const float* __restrict__ v1, float* o1,
                       const float* __restrict__ v2, float* o2) {
    const float* v = blockIdx.x ? v2 : v1;
    float* o = blockIdx.x ? o2 : o1;
    int t = threadIdx.x;
    float m = -FLT_MAX;
    for (int i = t; i < NPTS; i += 256) m = fmaxf(m, v[i]);
    for (int of = 16; of; of >>= 1) m = fmaxf(m, __shfl_xor_sync(0xffffffffu, m, of));
    __shared__ float sm[8];
    if ((t & 31) == 0) sm[t >> 5] = m;
    __syncthreads();
    if (t == 0) {
        float r = sm[0];
        for (int q = 1; q < 8; q++) r = fmaxf(r, sm[q]);
        *o = r;
    }
}

__device__ __forceinline__ float lrelu(float x) { return x > 0.f ? x : 0.2f * x; }

template <int D>
__global__ void k_att(const float* __restrict__ s, const float* __restrict__ t,
                      const float* __restrict__ rho,
                      const float* pSmax, const float* pTmax, const float* pRmax,
                      const float* __restrict__ val, int ldv,
                      float* __restrict__ out, int ldo) {
    int row = blockIdx.x * 4 + (threadIdx.x >> 5);
    int lane = threadIdx.x & 31;
    float ax_max = lrelu(*pSmax + *pTmax);
    float rt = rho[row] / (*pRmax) * ax_max;
    float si = s[row];
    int beg = g_roff[row], end = g_roff[row + 1];
    float m = -FLT_MAX;
    for (int k = beg + lane; k < end; k += 32)
        m = fmaxf(m, lrelu(si + t[g_redge[k]]) + rt);
    for (int o = 16; o; o >>= 1) m = fmaxf(m, __shfl_xor_sync(0xffffffffu, m, o));
    float Z = 0.f;
    for (int k = beg + lane; k < end; k += 32)
        Z += expf(lrelu(si + t[g_redge[k]]) + rt - m);
    for (int o = 16; o; o >>= 1) Z += __shfl_xor_sync(0xffffffffu, Z, o);
    const int CH = D / 32;
    float acc[CH];
#pragma unroll
    for (int j = 0; j < CH; j++) acc[j] = 0.f;
    for (int k = beg; k < end; k++) {
        int e = g_redge[k];
        float w = expf(lrelu(si + t[e]) + rt - m);
        const float* v = &val[(size_t)e * ldv];
#pragma unroll
        for (int j = 0; j < CH; j++) acc[j] += w * v[lane + j * 32];
    }
    float iz = 1.f / Z;
#pragma unroll
    for (int j = 0; j < CH; j++) {
        float x = acc[j] * iz;
        out[(size_t)row * ldo + lane + j * 32] = x > 0.f ? x : expm1f(x);
    }
}

// ---------------- host orchestration ----------------
extern "C" void kernel_launch(void* const* d_in, const int* in_sizes, int n_in,
                              void* d_out, int out_size) {
    const float* X     = (const float*)d_in[0];
    const float* theta = (const float*)d_in[1];
    const float* Wh    = (const float*)d_in[2];
    const float* axh   = (const float*)d_in[3];
    const float* aeh   = (const float*)d_in[4];
    const float* W2    = (const float*)d_in[5];
    const float* ax2   = (const float*)d_in[6];
    const float* ae2   = (const float*)d_in[7];
    float* out = (float*)d_out;
    (void)in_sizes; (void)n_in; (void)out_size;

    void* vp;
    cudaGetSymbolAddress(&vp, g_XT);   float* XT   = (float*)vp;
    cudaGetSymbolAddress(&vp, g_Xe);   float* Xe   = (float*)vp;
    cudaGetSymbolAddress(&vp, g_E);    float* E    = (float*)vp;
    cudaGetSymbolAddress(&vp, g_nrm);  float* nrm  = (float*)vp;
    cudaGetSymbolAddress(&vp, g_rho);  float* rho  = (float*)vp;
    cudaGetSymbolAddress(&vp, g_rhoe); float* rhoe = (float*)vp;
    cudaGetSymbolAddress(&vp, g_P);    float* P    = (float*)vp;
    cudaGetSymbolAddress(&vp, g_Q);    float* Q    = (float*)vp;
    cudaGetSymbolAddress(&vp, g_sv);   float* sv   = (float*)vp;
    cudaGetSymbolAddress(&vp, g_tv);   float* tv   = (float*)vp;
    cudaGetSymbolAddress(&vp, g_Enew); float* Enew = (float*)vp;
    cudaGetSymbolAddress(&vp, g_Xcat); float* Xcat = (float*)vp;
    cudaGetSymbolAddress(&vp, g_scal); float* scal = (float*)vp;

    // ---- HGCN ----
    k_init<<<4096, 256>>>();
    k_rowsq<<<NPTS / 4, 128>>>(X);
    k_aat_dist_sym<<<528, 256>>>(X);
    k_topk<<<NPTS, 256>>>();
    k_deg<<<(NPTS * KP1 + 255) / 256, 256>>>();
    k_scan<<<1, 1024>>>();
    k_fill<<<NPTS, 128>>>();
    k_gemm128<<<dim3(2, 32), 256>>>(X, theta, XT, DIN, DHID);
    k_gather_edges<<<NPTS / 4, 128>>>();
    k_gather_nodes<<<NPTS / 4, 128>>>();

    // ---- densities (stage 1) ----
    k_rownorm<<<NPTS / 4, 128>>>(Xe, nrm);
    k_density<<<NPTS, 256>>>(Xe, nrm);
    k_rhoe<<<NPTS / 256, 256>>>();
    k_max2<<<2, 256>>>(rho, scal + 2, rhoe, scal + 3);

    // ---- all-head projections in 2 GEMMs ----
    k_gemm_heads<<<dim3(2, 32), 256>>>(Xe, Wh, P);
    k_gemm_heads<<<dim3(2, 32), 256>>>(E, Wh, Q);

    // ---- 4 attention heads ----
    for (int h = 0; h < MH; h++) {
        const float* ax = axh + (size_t)h * 2 * DHEAD;
        const float* ae = aeh + (size_t)h * 2 * DHEAD;
        // attention 1: nodes attend over edges; val = P-slice
        k_sv_tv<<<2048, 128>>>(P + h * DHEAD, ax, Q + h * DHEAD, ax + DHEAD, DHID, DHEAD);
        k_max2<<<2, 256>>>(sv, scal + 0, tv, scal + 1);
        k_att<DHEAD><<<NPTS / 4, 128>>>(sv, tv, rho, scal + 0, scal + 1, scal + 2,
                                        P + h * DHEAD, DHID, Enew, DHEAD);
        // attention 2: edges attend over nodes; val = Enew
        k_sv_tv<<<2048, 128>>>(Q + h * DHEAD, ae, P + h * DHEAD, ae + DHEAD, DHID, DHEAD);
        k_max2<<<2, 256>>>(sv, scal + 0, tv, scal + 1);
        k_att<DHEAD><<<NPTS / 4, 128>>>(sv, tv, rhoe, scal + 0, scal + 1, scal + 3,
                                        Enew, DHEAD, Xcat + h * DHEAD, DHID);
    }

    // ---- final DA-HGAN layer (d = 256) ----
    k_rownorm<<<NPTS / 4, 128>>>(Xcat, nrm);
    k_density<<<NPTS, 256>>>(Xcat, nrm);
    k_rhoe<<<NPTS / 256, 256>>>();
    k_max2<<<2, 256>>>(rho, scal + 2, rhoe, scal + 3);

    k_gemm128<<<dim3(2, 32), 256>>>(Xcat, W2, P, DHID, DHID);
    k_gemm128<<<dim3(2, 32), 256>>>(E, W2, Q, DHID, DHID);

    k_sv_tv<<<2048, 128>>>(P, ax2, Q, ax2 + DHID, DHID, DHID);
    k_max2<<<2, 256>>>(sv, scal + 0, tv, scal + 1);
    k_att<DHID><<<NPTS / 4, 128>>>(sv, tv, rho, scal + 0, scal + 1, scal + 2,
                                   P, DHID, Enew, DHID);

    k_sv_tv<<<2048, 128>>>(Q, ae2, P, ae2 + DHID, DHID, DHID);
    k_max2<<<2, 256>>>(sv, scal + 0, tv, scal + 1);
    k_att<DHID><<<NPTS / 4, 128>>>(sv, tv, rhoe, scal + 0, scal + 1, scal + 3,
                                   Enew, DHID, out, DHID);
}

// round 3
// speedup vs baseline: 1.4573x; 1.3260x over previous
#include <cuda_runtime.h>
#include <math.h>
#include <float.h>

// ---------------- problem constants ----------------
#define NPTS  4096
#define DIN   784
#define DHID  256
#define MH    4
#define DHEAD 64
#define KP1   11
#define SIGMA_C 0.1f
#define DE_C  0.30151134457776363f   // 1/sqrt(11)

// ---------------- device scratch ----------------
__device__ float g_dist[(size_t)NPTS * NPTS];  // 64MB; after topk reused as int nbr[4096][4096]
__device__ float g_sq[NPTS];
__device__ int   g_idx[NPTS * KP1];
__device__ int   g_deg[NPTS];
__device__ float g_dv[NPTS];
__device__ int   g_roff[NPTS + 1];
__device__ int   g_cursor[NPTS];
__device__ int   g_redge[NPTS * KP1];
__device__ int   g_ncnt[NPTS];
__device__ float g_XT[NPTS * DHID];
__device__ float g_Xe[NPTS * DHID];
__device__ float g_E[NPTS * DHID];
__device__ float g_nrm[NPTS];
__device__ float g_rho[NPTS];
__device__ float g_rhoe[NPTS];
__device__ float g_P[NPTS * DHID];
__device__ float g_Q[NPTS * DHID];
__device__ float g_svh[MH * NPTS];
__device__ float g_tvh[MH * NPTS];
__device__ float g_Enew[NPTS * DHID];
__device__ float g_Xcat[NPTS * DHID];
__device__ float g_scal[16];  // [0..3]=smax/head [4..7]=tmax/head [8]=rho_max [9]=rhoe_max

// ---------------- small kernels ----------------
__global__ void k_rowsq(const float* __restrict__ X) {
    int gid = blockIdx.x * 128 + threadIdx.x;
    if (gid < NPTS) g_deg[gid] = 0;
    int row = blockIdx.x * 4 + (threadIdx.x >> 5);
    int lane = threadIdx.x & 31;
    float a = 0.f;
    for (int c = lane; c < DIN; c += 32) { float v = X[(size_t)row * DIN + c]; a += v * v; }
    for (int o = 16; o; o >>= 1) a += __shfl_xor_sync(0xffffffffu, a, o);
    if (lane == 0) g_sq[row] = a;
}

// ---- symmetric dist GEMM: upper-tri 128x128 blocks, mirrored f4 writes ----
__global__ __launch_bounds__(256) void k_aat_dist_sym(const float* __restrict__ A) {
    __shared__ float As[2][16][128];
    __shared__ float Bs[2][16][128];
    int b = blockIdx.x, by = 0;
    while (b >= 32 - by) { b -= 32 - by; ++by; }
    int bx = by + b;
    int row0 = by * 128, col0 = bx * 128;
    int t = threadIdx.x;
    int ty = t >> 4, tx = t & 15;
    int ra = t >> 2, qa = (t & 3) * 4;

    float4 pa0, pa1, pb0, pb1;
    pa0 = *(const float4*)&A[(size_t)(row0 + ra) * DIN + qa];
    pa1 = *(const float4*)&A[(size_t)(row0 + ra + 64) * DIN + qa];
    pb0 = *(const float4*)&A[(size_t)(col0 + ra) * DIN + qa];
    pb1 = *(const float4*)&A[(size_t)(col0 + ra + 64) * DIN + qa];
    As[0][qa + 0][ra] = pa0.x; As[0][qa + 1][ra] = pa0.y; As[0][qa + 2][ra] = pa0.z; As[0][qa + 3][ra] = pa0.w;
    As[0][qa + 0][ra + 64] = pa1.x; As[0][qa + 1][ra + 64] = pa1.y; As[0][qa + 2][ra + 64] = pa1.z; As[0][qa + 3][ra + 64] = pa1.w;
    Bs[0][qa + 0][ra] = pb0.x; Bs[0][qa + 1][ra] = pb0.y; Bs[0][qa + 2][ra] = pb0.z; Bs[0][qa + 3][ra] = pb0.w;
    Bs[0][qa + 0][ra + 64] = pb1.x; Bs[0][qa + 1][ra + 64] = pb1.y; Bs[0][qa + 2][ra + 64] = pb1.z; Bs[0][qa + 3][ra + 64] = pb1.w;
    __syncthreads();

    float acc[8][8];
#pragma unroll
    for (int i = 0; i < 8; i++)
#pragma unroll
        for (int j = 0; j < 8; j++) acc[i][j] = 0.f;

    const int nIt = DIN / 16;
    for (int it = 0; it < nIt; ++it) {
        int k0n = (it + 1) * 16;
        if (it + 1 < nIt) {
            pa0 = *(const float4*)&A[(size_t)(row0 + ra) * DIN + k0n + qa];
            pa1 = *(const float4*)&A[(size_t)(row0 + ra + 64) * DIN + k0n + qa];
            pb0 = *(const float4*)&A[(size_t)(col0 + ra) * DIN + k0n + qa];
            pb1 = *(const float4*)&A[(size_t)(col0 + ra + 64) * DIN + k0n + qa];
        }
        int buf = it & 1;
#pragma unroll
        for (int kk = 0; kk < 16; ++kk) {
            float4 a0 = *(const float4*)&As[buf][kk][ty * 8];
            float4 a1 = *(const float4*)&As[buf][kk][ty * 8 + 4];
            float4 b0 = *(const float4*)&Bs[buf][kk][tx * 8];
            float4 b1 = *(const float4*)&Bs[buf][kk][tx * 8 + 4];
            float ar[8] = {a0.x, a0.y, a0.z, a0.w, a1.x, a1.y, a1.z, a1.w};
            float br[8] = {b0.x, b0.y, b0.z, b0.w, b1.x, b1.y, b1.z, b1.w};
#pragma unroll
            for (int i = 0; i < 8; i++)
#pragma unroll
                for (int j = 0; j < 8; j++) acc[i][j] += ar[i] * br[j];
        }
        if (it + 1 < nIt) {
            int nb = buf ^ 1;
            As[nb][qa + 0][ra] = pa0.x; As[nb][qa + 1][ra] = pa0.y; As[nb][qa + 2][ra] = pa0.z; As[nb][qa + 3][ra] = pa0.w;
            As[nb][qa + 0][ra + 64] = pa1.x; As[nb][qa + 1][ra + 64] = pa1.y; As[nb][qa + 2][ra + 64] = pa1.z; As[nb][qa + 3][ra + 64] = pa1.w;
            Bs[nb][qa + 0][ra] = pb0.x; Bs[nb][qa + 1][ra] = pb0.y; Bs[nb][qa + 2][ra] = pb0.z; Bs[nb][qa + 3][ra] = pb0.w;
            Bs[nb][qa + 0][ra + 64] = pb1.x; Bs[nb][qa + 1][ra + 64] = pb1.y; Bs[nb][qa + 2][ra + 64] = pb1.z; Bs[nb][qa + 3][ra + 64] = pb1.w;
        }
        __syncthreads();
    }

    float si_[8], sj_[8];
#pragma unroll
    for (int i = 0; i < 8; i++) si_[i] = g_sq[row0 + ty * 8 + i];
#pragma unroll
    for (int j = 0; j < 8; j++) sj_[j] = g_sq[col0 + tx * 8 + j];

#pragma unroll
    for (int i = 0; i < 8; i++) {
        int gi = row0 + ty * 8 + i;
        float4 w0, w1;
        w0.x = fabsf(si_[i] + sj_[0] - 2.f * acc[i][0]);
        w0.y = fabsf(si_[i] + sj_[1] - 2.f * acc[i][1]);
        w0.z = fabsf(si_[i] + sj_[2] - 2.f * acc[i][2]);
        w0.w = fabsf(si_[i] + sj_[3] - 2.f * acc[i][3]);
        w1.x = fabsf(si_[i] + sj_[4] - 2.f * acc[i][4]);
        w1.y = fabsf(si_[i] + sj_[5] - 2.f * acc[i][5]);
        w1.z = fabsf(si_[i] + sj_[6] - 2.f * acc[i][6]);
        w1.w = fabsf(si_[i] + sj_[7] - 2.f * acc[i][7]);
        *(float4*)&g_dist[(size_t)gi * NPTS + col0 + tx * 8] = w0;
        *(float4*)&g_dist[(size_t)gi * NPTS + col0 + tx * 8 + 4] = w1;
    }
#pragma unroll
    for (int j = 0; j < 8; j++) {
        int gj = col0 + tx * 8 + j;
        float4 w0, w1;
        w0.x = fabsf(si_[0] + sj_[j] - 2.f * acc[0][j]);
        w0.y = fabsf(si_[1] + sj_[j] - 2.f * acc[1][j]);
        w0.z = fabsf(si_[2] + sj_[j] - 2.f * acc[2][j]);
        w0.w = fabsf(si_[3] + sj_[j] - 2.f * acc[3][j]);
        w1.x = fabsf(si_[4] + sj_[j] - 2.f * acc[4][j]);
        w1.y = fabsf(si_[5] + sj_[j] - 2.f * acc[5][j]);
        w1.z = fabsf(si_[6] + sj_[j] - 2.f * acc[6][j]);
        w1.w = fabsf(si_[7] + sj_[j] - 2.f * acc[7][j]);
        *(float4*)&g_dist[(size_t)gj * NPTS + row0 + ty * 8] = w0;
        *(float4*)&g_dist[(size_t)gj * NPTS + row0 + ty * 8 + 4] = w1;
    }
}

// ---- top-11 per row ----
__device__ __forceinline__ bool pless(float av, int ai, float bv, int bi) {
    return av < bv || (av == bv && ai < bi);
}

__global__ void k_topk() {
    __shared__ float lvS[KP1 * 256];
    __shared__ int   liS[KP1 * 256];
    __shared__ float wv[8];
    __shared__ int   wi[8];
    __shared__ int   sel;
    int row = blockIdx.x, t = threadIdx.x;
    const float* drow = &g_dist[(size_t)row * NPTS];
    float lv[KP1]; int li[KP1];
#pragma unroll
    for (int q = 0; q < KP1; q++) { lv[q] = FLT_MAX; li[q] = 0x7fffffff; }
#pragma unroll
    for (int s = 0; s < 16; s++) {
        int j = t + (s << 8);
        float v = drow[j];
        if (pless(v, j, lv[KP1 - 1], li[KP1 - 1])) {
            lv[KP1 - 1] = v; li[KP1 - 1] = j;
#pragma unroll
            for (int q = KP1 - 1; q > 0; q--) {
                if (pless(lv[q], li[q], lv[q - 1], li[q - 1])) {
                    float tv_ = lv[q]; lv[q] = lv[q - 1]; lv[q - 1] = tv_;
                    int ti_ = li[q]; li[q] = li[q - 1]; li[q - 1] = ti_;
                }
            }
        }
    }
#pragma unroll
    for (int q = 0; q < KP1; q++) { lvS[q * 256 + t] = lv[q]; liS[q * 256 + t] = li[q]; }
    __syncthreads();
    int p = 0;
    for (int it = 0; it < KP1; ++it) {
        float v = (p < KP1) ? lvS[p * 256 + t] : FLT_MAX;
        int ix = (p < KP1) ? liS[p * 256 + t] : 0x7fffffff;
#pragma unroll
        for (int o = 16; o; o >>= 1) {
            float ov = __shfl_xor_sync(0xffffffffu, v, o);
            int oi = __shfl_xor_sync(0xffffffffu, ix, o);
            if (pless(ov, oi, v, ix)) { v = ov; ix = oi; }
        }
        if ((t & 31) == 0) { wv[t >> 5] = v; wi[t >> 5] = ix; }
        __syncthreads();
        if (t < 32) {
            float v2 = t < 8 ? wv[t] : FLT_MAX;
            int i2 = t < 8 ? wi[t] : 0x7fffffff;
#pragma unroll
            for (int o = 4; o; o >>= 1) {
                float ov = __shfl_xor_sync(0xffffffffu, v2, o);
                int oi = __shfl_xor_sync(0xffffffffu, i2, o);
                if (pless(ov, oi, v2, i2)) { v2 = ov; i2 = oi; }
            }
            if (t == 0) { g_idx[row * KP1 + it] = i2; sel = i2; }
        }
        __syncthreads();
        if (p < KP1 && liS[p * 256 + t] == sel) p++;
    }
}

__global__ void k_deg() {
    int i = blockIdx.x * blockDim.x + threadIdx.x;
    if (i < NPTS * KP1) atomicAdd(&g_deg[g_idx[i]], 1);
}

// parallel exclusive scan of deg (4096 elems) + dv + cursor
__global__ void k_scan() {
    __shared__ int s[1024];
    int t = threadIdx.x;
    int base = t * 4;
    int v0 = g_deg[base], v1 = g_deg[base + 1], v2 = g_deg[base + 2], v3 = g_deg[base + 3];
    int sum = v0 + v1 + v2 + v3;
    s[t] = sum;
    __syncthreads();
    for (int off = 1; off < 1024; off <<= 1) {
        int x = (t >= off) ? s[t - off] : 0;
        __syncthreads();
        s[t] += x;
        __syncthreads();
    }
    int run = s[t] - sum;   // exclusive
    g_roff[base] = run; g_cursor[base] = run; g_dv[base] = rsqrtf((float)v0); run += v0;
    g_roff[base + 1] = run; g_cursor[base + 1] = run; g_dv[base + 1] = rsqrtf((float)v1); run += v1;
    g_roff[base + 2] = run; g_cursor[base + 2] = run; g_dv[base + 2] = rsqrtf((float)v2); run += v2;
    g_roff[base + 3] = run; g_cursor[base + 3] = run; g_dv[base + 3] = rsqrtf((float)v3); run += v3;
    if (t == 1023) g_roff[NPTS] = run;
}

__global__ void k_fill() {
    int e = blockIdx.x, t = threadIdx.x;  // 32 threads
    if (t < KP1) {
        int i = g_idx[e * KP1 + t];
        int p = atomicAdd(&g_cursor[i], 1);
        g_redge[p] = e;
    }
}

// build dedup'd ascending neighbor lists into g_dist region
__global__ void k_nbr() {
    __shared__ unsigned bm[128];
    __shared__ int wsum[4];
    int i = blockIdx.x, t = threadIdx.x;   // 128 threads
    bm[t] = 0u;
    __syncthreads();
    int beg = g_roff[i];
    int cnt = (g_roff[i + 1] - beg) * KP1;
    for (int p = t; p < cnt; p += 128) {
        int e = g_redge[beg + p / KP1];
        int m = g_idx[e * KP1 + p % KP1];
        atomicOr(&bm[m >> 5], 1u << (m & 31));
    }
    __syncthreads();
    if (t == 0) bm[i >> 5] &= ~(1u << (i & 31));   // drop self
    __syncthreads();
    unsigned w = bm[t];
    int pc = __popc(w);
    int lane = t & 31, wid = t >> 5;
    int sc = pc;
    for (int o = 1; o < 32; o <<= 1) {
        int x = __shfl_up_sync(0xffffffffu, sc, o);
        if (lane >= o) sc += x;
    }
    if (lane == 31) wsum[wid] = sc;
    __syncthreads();
    int woff = 0;
    for (int q = 0; q < wid; q++) woff += wsum[q];
    int off = woff + sc - pc;
    int* nbr = (int*)g_dist + (size_t)i * NPTS;
    while (w) {
        int b = __ffs(w) - 1; w &= w - 1;
        nbr[off++] = t * 32 + b;
    }
    if (t == 127) g_ncnt[i] = woff + sc;
}

// ---- 128x64 GEMM, double buffered ----
__global__ __launch_bounds__(256) void k_gemm64(const float* __restrict__ A,
                                                const float* __restrict__ B,
                                                float* __restrict__ C, int K, int Np) {
    __shared__ float As[2][16][128];
    __shared__ float Bs[2][16][64];
    int t = threadIdx.x;
    int m0 = blockIdx.y * 128, n0 = blockIdx.x * 64;
    int ty = t >> 4, tx = t & 15;
    int ra = t >> 1, qa = (t & 1) * 8;
    int kb = t >> 4, cb = (t & 15) * 4;

    float4 pa0, pa1, pb;
    pa0 = *(const float4*)&A[(size_t)(m0 + ra) * K + qa];
    pa1 = *(const float4*)&A[(size_t)(m0 + ra) * K + qa + 4];
    pb = *(const float4*)&B[(size_t)kb * Np + n0 + cb];
    As[0][qa + 0][ra] = pa0.x; As[0][qa + 1][ra] = pa0.y; As[0][qa + 2][ra] = pa0.z; As[0][qa + 3][ra] = pa0.w;
    As[0][qa + 4][ra] = pa1.x; As[0][qa + 5][ra] = pa1.y; As[0][qa + 6][ra] = pa1.z; As[0][qa + 7][ra] = pa1.w;
    *(float4*)&Bs[0][kb][cb] = pb;
    __syncthreads();

    float acc[8][4];
#pragma unroll
    for (int i = 0; i < 8; i++)
#pragma unroll
        for (int j = 0; j < 4; j++) acc[i][j] = 0.f;

    int nIt = K / 16;
    for (int it = 0; it < nIt; ++it) {
        int k0n = (it + 1) * 16;
        if (it + 1 < nIt) {
            pa0 = *(const float4*)&A[(size_t)(m0 + ra) * K + k0n + qa];
            pa1 = *(const float4*)&A[(size_t)(m0 + ra) * K + k0n + qa + 4];
            pb = *(const float4*)&B[(size_t)(k0n + kb) * Np + n0 + cb];
        }
        int buf = it & 1;
#pragma unroll
        for (int kk = 0; kk < 16; ++kk) {
            float4 a0 = *(const float4*)&As[buf][kk][ty * 8];
            float4 a1 = *(const float4*)&As[buf][kk][ty * 8 + 4];
            float4 b0 = *(const float4*)&Bs[buf][kk][tx * 4];
            float ar[8] = {a0.x, a0.y, a0.z, a0.w, a1.x, a1.y, a1.z, a1.w};
            float br[4] = {b0.x, b0.y, b0.z, b0.w};
#pragma unroll
            for (int i = 0; i < 8; i++)
#pragma unroll
                for (int j = 0; j < 4; j++) acc[i][j] += ar[i] * br[j];
        }
        if (it + 1 < nIt) {
            int nb = buf ^ 1;
            As[nb][qa + 0][ra] = pa0.x; As[nb][qa + 1][ra] = pa0.y; As[nb][qa + 2][ra] = pa0.z; As[nb][qa + 3][ra] = pa0.w;
            As[nb][qa + 4][ra] = pa1.x; As[nb][qa + 5][ra] = pa1.y; As[nb][qa + 6][ra] = pa1.z; As[nb][qa + 7][ra] = pa1.w;
            *(float4*)&Bs[nb][kb][cb] = pb;
        }
        __syncthreads();
    }
#pragma unroll
    for (int i = 0; i < 8; i++) {
        float4 w0 = {acc[i][0], acc[i][1], acc[i][2], acc[i][3]};
        *(float4*)&C[(size_t)(m0 + ty * 8 + i) * Np + n0 + tx * 4] = w0;
    }
}

// heads variant: tile bx = head h; B = Wh[h] (256x64); C cols h*64.., ld 256
__global__ __launch_bounds__(256) void k_gemm64h(const float* __restrict__ A,
                                                 const float* __restrict__ Wh,
                                                 float* __restrict__ C) {
    __shared__ float As[2][16][128];
    __shared__ float Bs[2][16][64];
    int t = threadIdx.x;
    int m0 = blockIdx.y * 128, h = blockIdx.x;
    const float* B = Wh + (size_t)h * DHID * 64;
    int ty = t >> 4, tx = t & 15;
    int ra = t >> 1, qa = (t & 1) * 8;
    int kb = t >> 4, cb = (t & 15) * 4;
    const int K = DHID;

    float4 pa0, pa1, pb;
    pa0 = *(const float4*)&A[(size_t)(m0 + ra) * K + qa];
    pa1 = *(const float4*)&A[(size_t)(m0 + ra) * K + qa + 4];
    pb = *(const float4*)&B[(size_t)kb * 64 + cb];
    As[0][qa + 0][ra] = pa0.x; As[0][qa + 1][ra] = pa0.y; As[0][qa + 2][ra] = pa0.z; As[0][qa + 3][ra] = pa0.w;
    As[0][qa + 4][ra] = pa1.x; As[0][qa + 5][ra] = pa1.y; As[0][qa + 6][ra] = pa1.z; As[0][qa + 7][ra] = pa1.w;
    *(float4*)&Bs[0][kb][cb] = pb;
    __syncthreads();

    float acc[8][4];
#pragma unroll
    for (int i = 0; i < 8; i++)
#pragma unroll
        for (int j = 0; j < 4; j++) acc[i][j] = 0.f;

    const int nIt = K / 16;
    for (int it = 0; it < nIt; ++it) {
        int k0n = (it + 1) * 16;
        if (it + 1 < nIt) {
            pa0 = *(const float4*)&A[(size_t)(m0 + ra) * K + k0n + qa];
            pa1 = *(const float4*)&A[(size_t)(m0 + ra) * K + k0n + qa + 4];
            pb = *(const float4*)&B[(size_t)(k0n + kb) * 64 + cb];
        }
        int buf = it & 1;
#pragma unroll
        for (int kk = 0; kk < 16; ++kk) {
            float4 a0 = *(const float4*)&As[buf][kk][ty * 8];
            float4 a1 = *(const float4*)&As[buf][kk][ty * 8 + 4];
            float4 b0 = *(const float4*)&Bs[buf][kk][tx * 4];
            float ar[8] = {a0.x, a0.y, a0.z, a0.w, a1.x, a1.y, a1.z, a1.w};
            float br[4] = {b0.x, b0.y, b0.z, b0.w};
#pragma unroll
            for (int i = 0; i < 8; i++)
#pragma unroll
                for (int j = 0; j < 4; j++) acc[i][j] += ar[i] * br[j];
        }
        if (it + 1 < nIt) {
            int nb = buf ^ 1;
            As[nb][qa + 0][ra] = pa0.x; As[nb][qa + 1][ra] = pa0.y; As[nb][qa + 2][ra] = pa0.z; As[nb][qa + 3][ra] = pa0.w;
            As[nb][qa + 4][ra] = pa1.x; As[nb][qa + 5][ra] = pa1.y; As[nb][qa + 6][ra] = pa1.z; As[nb][qa + 7][ra] = pa1.w;
            *(float4*)&Bs[nb][kb][cb] = pb;
        }
        __syncthreads();
    }
#pragma unroll
    for (int i = 0; i < 8; i++) {
        float4 w0 = {acc[i][0], acc[i][1], acc[i][2], acc[i][3]};
        *(float4*)&C[(size_t)(m0 + ty * 8 + i) * DHID + h * 64 + tx * 4] = w0;
    }
}

// ---- hypergraph gathers ----
__global__ void k_gather_edges() {
    int e = blockIdx.x * 4 + (threadIdx.x >> 5);
    int lane = threadIdx.x & 31;
    float acc[8] = {};
    for (int k = 0; k < KP1; k++) {
        int i = g_idx[e * KP1 + k];
        float w = g_dv[i];
        const float* r = &g_XT[(size_t)i * DHID];
#pragma unroll
        for (int j = 0; j < 8; j++) acc[j] += w * r[lane + j * 32];
    }
#pragma unroll
    for (int j = 0; j < 8; j++) g_Xe[(size_t)e * DHID + lane + j * 32] = DE_C * acc[j];
}

__global__ void k_gather_nodes() {
    int i = blockIdx.x * 4 + (threadIdx.x >> 5);
    int lane = threadIdx.x & 31;
    int beg = g_roff[i], end = g_roff[i + 1];
    float acc[8] = {};
    for (int k = beg; k < end; k++) {
        const float* r = &g_Xe[(size_t)g_redge[k] * DHID];
#pragma unroll
        for (int j = 0; j < 8; j++) acc[j] += r[lane + j * 32];
    }
    float s = g_dv[i] * DE_C;
#pragma unroll
    for (int j = 0; j < 8; j++) g_E[(size_t)i * DHID + lane + j * 32] = s * acc[j];
}

__global__ void k_rownorm(const float* __restrict__ Xf) {
    int row = blockIdx.x * 4 + (threadIdx.x >> 5);
    int lane = threadIdx.x & 31;
    float a = 0.f;
    for (int c = lane; c < DHID; c += 32) { float v = Xf[(size_t)row * DHID + c]; a += v * v; }
    for (int o = 16; o; o >>= 1) a += __shfl_xor_sync(0xffffffffu, a, o);
    if (lane == 0) g_nrm[row] = sqrtf(a);
}

// density from neighbor lists (deterministic tree sum)
__global__ void k_density(const float* __restrict__ Xf) {
    __shared__ float xs[DHID];
    __shared__ float ps[8];
    int i = blockIdx.x, t = threadIdx.x;   // 256
    xs[t] = Xf[(size_t)i * DHID + t];
    __syncthreads();
    int lane = t & 31, wp = t >> 5;
    const int* nbr = (const int*)g_dist + (size_t)i * NPTS;
    int n = g_ncnt[i];
    float ni = g_nrm[i], part = 0.f;
    for (int e = wp; e < n; e += 8) {
        int j = nbr[e];
        const float* r = &Xf[(size_t)j * DHID];
        float d = 0.f;
#pragma unroll
        for (int c = 0; c < 8; c++) d += xs[lane + c * 32] * r[lane + c * 32];
        for (int o = 16; o; o >>= 1) d += __shfl_xor_sync(0xffffffffu, d, o);
        if (lane == 0) {
            float cs = d / (ni * g_nrm[j]);
            if (cs > SIGMA_C) part += cs;
        }
    }
    if (lane == 0) ps[wp] = part;
    __syncthreads();
    if (t == 0) {
        float a = 0.f;
        for (int q = 0; q < 8; q++) a += ps[q];
        g_rho[i] = a;
    }
}

__global__ void k_rhoe() {
    int e = blockIdx.x * blockDim.x + threadIdx.x;
    if (e < NPTS) {
        float r = 0.f;
        for (int k = 0; k < KP1; k++) r += g_rho[g_idx[e * KP1 + k]];
        g_rhoe[e] = r;
    }
}

__global__ void k_max2(const float* __restrict__ v1, float* o1,
                       const float* __restrict__ v2, float* o2) {
    const float* v = blockIdx.x ? v2 : v1;
    float* o = blockIdx.x ? o2 : o1;
    int t = threadIdx.x;
    float m = -FLT_MAX;
    for (int i = t; i < NPTS; i += 256) m = fmaxf(m, v[i]);
    for (int of = 16; of; of >>= 1) m = fmaxf(m, __shfl_xor_sync(0xffffffffu, m, of));
    __shared__ float sm[8];
    if ((t & 31) == 0) sm[t >> 5] = m;
    __syncthreads();
    if (t == 0) {
        float r = sm[0];
        for (int q = 1; q < 8; q++) r = fmaxf(r, sm[q]);
        *o = r;
    }
}

// all-heads s/t matvec (D=64); g = warp>>12: h=g&3, which=g>>2
__global__ void k_svtv4(const float* __restrict__ Ms, const float* __restrict__ Mt,
                        const float* __restrict__ av) {
    int w = (blockIdx.x * 256 + threadIdx.x) >> 5;
    int lane = threadIdx.x & 31;
    int row = w & (NPTS - 1);
    int g = w >> 12;
    int h = g & 3, which = g >> 2;
    const float* M = which ? Mt : Ms;
    const float* a = av + (size_t)h * 2 * DHEAD + which * DHEAD;
    const float* r = M + (size_t)row * DHID + h * DHEAD;
    float p = r[lane] * a[lane] + r[lane + 32] * a[lane + 32];
    for (int o = 16; o; o >>= 1) p += __shfl_xor_sync(0xffffffffu, p, o);
    if (lane == 0) (which ? g_tvh : g_svh)[h * NPTS + row] = p;
}

// single (final) s/t matvec D=256 -> g_svh[0..], g_tvh[0..]
__global__ void k_svtv1(const float* __restrict__ Ms, const float* __restrict__ as,
                        const float* __restrict__ Mt, const float* __restrict__ at) {
    int w = (blockIdx.x * 256 + threadIdx.x) >> 5;
    int lane = threadIdx.x & 31;
    int row = w & (NPTS - 1);
    int which = w >> 12;
    const float* M = which ? Mt : Ms;
    const float* a = which ? at : as;
    const float* r = M + (size_t)row * DHID;
    float p = 0.f;
#pragma unroll
    for (int c = 0; c < 8; c++) p += r[lane + c * 32] * a[lane + c * 32];
    for (int o = 16; o; o >>= 1) p += __shfl_xor_sync(0xffffffffu, p, o);
    if (lane == 0) (which ? g_tvh : g_svh)[row] = p;
}

__global__ void k_max8() {
    int b = blockIdx.x, t = threadIdx.x;
    const float* v = (b < 4) ? (g_svh + b * NPTS) : (g_tvh + (b - 4) * NPTS);
    float m = -FLT_MAX;
    for (int i = t; i < NPTS; i += 256) m = fmaxf(m, v[i]);
    for (int of = 16; of; of >>= 1) m = fmaxf(m, __shfl_xor_sync(0xffffffffu, m, of));
    __shared__ float sm[8];
    if ((t & 31) == 0) sm[t >> 5] = m;
    __syncthreads();
    if (t == 0) {
        float r = sm[0];
        for (int q = 1; q < 8; q++) r = fmaxf(r, sm[q]);
        g_scal[b] = r;
    }
}

__device__ __forceinline__ float lrelu(float x) { return x > 0.f ? x : 0.2f * x; }

// all-heads attention: grid (1024, nheads); head h = blockIdx.y
template <int D>
__global__ void k_att4(const float* __restrict__ rho, const float* pR,
                       const float* __restrict__ valb, int ldv,
                       float* __restrict__ outb, int ldo, int hstride) {
    int h = blockIdx.y;
    int row = blockIdx.x * 4 + (threadIdx.x >> 5);
    int lane = threadIdx.x & 31;
    const float* sA = g_svh + h * NPTS;
    const float* tA = g_tvh + h * NPTS;
    float ax_max = lrelu(g_scal[h] + g_scal[4 + h]);
    float rt = rho[row] / (*pR) * ax_max;
    float si = sA[row];
    int beg = g_roff[row], end = g_roff[row + 1];
    int deg = end - beg;
    const float* val = valb + h * hstride;
    float* out = outb + h * hstride;
    const int CH = D / 32;
    float acc[CH];
#pragma unroll
    for (int j = 0; j < CH; j++) acc[j] = 0.f;
    float iz;
    if (deg <= 32) {
        int mye = (lane < deg) ? g_redge[beg + lane] : 0;
        float st = (lane < deg) ? (lrelu(si + tA[mye]) + rt) : -FLT_MAX;
        float m = st;
        for (int o = 16; o; o >>= 1) m = fmaxf(m, __shfl_xor_sync(0xffffffffu, m, o));
        float myw = (lane < deg) ? expf(st - m) : 0.f;
        float Z = myw;
        for (int o = 16; o; o >>= 1) Z += __shfl_xor_sync(0xffffffffu, Z, o);
        for (int k = 0; k < deg; k++) {
            int e = __shfl_sync(0xffffffffu, mye, k);
            float w = __shfl_sync(0xffffffffu, myw, k);
            const float* v = &val[(size_t)e * ldv];
#pragma unroll
            for (int j = 0; j < CH; j++) acc[j] += w * v[lane + j * 32];
        }
        iz = 1.f / Z;
    } else {
        float m = -FLT_MAX;
        for (int k = beg + lane; k < end; k += 32)
            m = fmaxf(m, lrelu(si + tA[g_redge[k]]) + rt);
        for (int o = 16; o; o >>= 1) m = fmaxf(m, __shfl_xor_sync(0xffffffffu, m, o));
        float Z = 0.f;
        for (int k = beg + lane; k < end; k += 32)
            Z += expf(lrelu(si + tA[g_redge[k]]) + rt - m);
        for (int o = 16; o; o >>= 1) Z += __shfl_xor_sync(0xffffffffu, Z, o);
        for (int k = beg; k < end; k++) {
            int e = g_redge[k];
            float w = expf(lrelu(si + tA[e]) + rt - m);
            const float* v = &val[(size_t)e * ldv];
#pragma unroll
            for (int j = 0; j < CH; j++) acc[j] += w * v[lane + j * 32];
        }
        iz = 1.f / Z;
    }
#pragma unroll
    for (int j = 0; j < CH; j++) {
        float x = acc[j] * iz;
        out[(size_t)row * ldo + lane + j * 32] = x > 0.f ? x : expm1f(x);
    }
}

// ---------------- host orchestration ----------------
extern "C" void kernel_launch(void* const* d_in, const int* in_sizes, int n_in,
                              void* d_out, int out_size) {
    const float* X     = (const float*)d_in[0];
    const float* theta = (const float*)d_in[1];
    const float* Wh    = (const float*)d_in[2];
    const float* axh   = (const float*)d_in[3];
    const float* aeh   = (const float*)d_in[4];
    const float* W2    = (const float*)d_in[5];
    const float* ax2   = (const float*)d_in[6];
    const float* ae2   = (const float*)d_in[7];
    float* out = (float*)d_out;
    (void)in_sizes; (void)n_in; (void)out_size;

    void* vp;
    cudaGetSymbolAddress(&vp, g_XT);   float* XT   = (float*)vp;
    cudaGetSymbolAddress(&vp, g_Xe);   float* Xe   = (float*)vp;
    cudaGetSymbolAddress(&vp, g_E);    float* E    = (float*)vp;
    cudaGetSymbolAddress(&vp, g_rho);  float* rho  = (float*)vp;
    cudaGetSymbolAddress(&vp, g_rhoe); float* rhoe = (float*)vp;
    cudaGetSymbolAddress(&vp, g_P);    float* P    = (float*)vp;
    cudaGetSymbolAddress(&vp, g_Q);    float* Q    = (float*)vp;
    cudaGetSymbolAddress(&vp, g_Enew); float* Enew = (float*)vp;
    cudaGetSymbolAddress(&vp, g_Xcat); float* Xcat = (float*)vp;
    cudaGetSymbolAddress(&vp, g_scal); float* scal = (float*)vp;

    // ---- HGCN ----
    k_rowsq<<<NPTS / 4, 128>>>(X);
    k_aat_dist_sym<<<528, 256>>>(X);
    k_topk<<<NPTS, 256>>>();
    k_deg<<<(NPTS * KP1 + 255) / 256, 256>>>();
    k_scan<<<1, 1024>>>();
    k_fill<<<NPTS, 32>>>();
    k_gemm64<<<dim3(4, 32), 256>>>(X, theta, XT, DIN, DHID);
    k_gather_edges<<<NPTS / 4, 128>>>();
    k_gather_nodes<<<NPTS / 4, 128>>>();
    k_nbr<<<NPTS, 128>>>();

    // ---- densities (stage 1) ----
    k_rownorm<<<NPTS / 4, 128>>>(Xe);
    k_density<<<NPTS, 256>>>(Xe);
    k_rhoe<<<NPTS / 256, 256>>>();
    k_max2<<<2, 256>>>(rho, scal + 8, rhoe, scal + 9);

    // ---- all-head projections ----
    k_gemm64h<<<dim3(4, 32), 256>>>(Xe, Wh, P);
    k_gemm64h<<<dim3(4, 32), 256>>>(E, Wh, Q);

    // ---- attention pass 1 (all heads) ----
    k_svtv4<<<4096, 256>>>(P, Q, axh);
    k_max8<<<8, 256>>>();
    k_att4<DHEAD><<<dim3(NPTS / 4, MH), 128>>>(rho, scal + 8, P, DHID, Enew, DHID, DHEAD);

    // ---- attention pass 2 (all heads) ----
    k_svtv4<<<4096, 256>>>(Q, P, aeh);
    k_max8<<<8, 256>>>();
    k_att4<DHEAD><<<dim3(NPTS / 4, MH), 128>>>(rhoe, scal + 9, Enew, DHID, Xcat, DHID, DHEAD);

    // ---- final DA-HGAN layer ----
    k_rownorm<<<NPTS / 4, 128>>>(Xcat);
    k_density<<<NPTS, 256>>>(Xcat);
    k_rhoe<<<NPTS / 256, 256>>>();
    k_max2<<<2, 256>>>(rho, scal + 8, rhoe, scal + 9);

    k_gemm64<<<dim3(4, 32), 256>>>(Xcat, W2, P, DHID, DHID);
    k_gemm64<<<dim3(4, 32), 256>>>(E, W2, Q, DHID, DHID);

    k_svtv1<<<1024, 256>>>(P, ax2, Q, ax2 + DHID);
    k_max8<<<8, 256>>>();
    k_att4<DHID><<<dim3(NPTS / 4, 1), 128>>>(rho, scal + 8, P, DHID, Enew, DHID, 0);

    k_svtv1<<<1024, 256>>>(Q, ae2, P, ae2 + DHID);
    k_max8<<<8, 256>>>();
    k_att4<DHID><<<dim3(NPTS / 4, 1), 128>>>(rhoe, scal + 9, Enew, DHID, out, DHID, 0);
}

// round 5
// speedup vs baseline: 1.5730x; 1.0794x over previous
#include <cuda_runtime.h>
#include <math.h>
#include <float.h>

// ---------------- problem constants ----------------
#define NPTS  4096
#define DIN   784
#define DHID  256
#define MH    4
#define DHEAD 64
#define KP1   11
#define SIGMA_C 0.1f
#define DE_C  0.30151134457776363f   // 1/sqrt(11)

// ---------------- device scratch ----------------
__device__ float g_dist[(size_t)NPTS * NPTS];  // 64MB; after topk reused as int nbr[4096][4096]
__device__ float g_sq[NPTS];
__device__ int   g_idx[NPTS * KP1];
__device__ int   g_deg[NPTS];
__device__ float g_dv[NPTS];
__device__ int   g_roff[NPTS + 1];
__device__ int   g_cursor[NPTS];
__device__ int   g_redge[NPTS * KP1];
__device__ int   g_ncnt[NPTS];
__device__ float g_XT[NPTS * DHID];
__device__ float g_Xe[NPTS * DHID];
__device__ float g_E[NPTS * DHID];
__device__ float g_nrm[NPTS];
__device__ float g_rho[NPTS];
__device__ float g_rhoe[NPTS];
__device__ float g_P[NPTS * DHID];
__device__ float g_Q[NPTS * DHID];
__device__ float g_svh[MH * NPTS];
__device__ float g_tvh[MH * NPTS];
__device__ float g_Enew[NPTS * DHID];
__device__ float g_Xcat[NPTS * DHID];
__device__ unsigned g_smax[32];   // encoded float maxima (monotone unsigned encoding)

// slots: [0..3] att1 s/head  [4..7] att1 t/head
//        [8..11] att2 s/head [12..15] att2 t/head
//        [16,17] fin1 s,t    [18,19] fin2 s,t
//        [20] rho1  [21] rhoe1  [22] rho2  [23] rhoe2

__device__ __forceinline__ unsigned encf(float f) {
    unsigned u = __float_as_uint(f);
    return (u & 0x80000000u) ? ~u : (u | 0x80000000u);
}
__device__ __forceinline__ float decf(unsigned u) {
    return __uint_as_float((u & 0x80000000u) ? (u & 0x7fffffffu) : ~u);
}

// ---------------- init ----------------
__global__ void k_zeroinit() {
    int t = threadIdx.x;
    for (int i = t; i < NPTS; i += 1024) g_deg[i] = 0;
    if (t < 32) g_smax[t] = 0u;
}

__global__ void k_rowsq(const float* __restrict__ X) {
    int row = blockIdx.x * 4 + (threadIdx.x >> 5);
    int lane = threadIdx.x & 31;
    float a = 0.f;
    for (int c = lane; c < DIN; c += 32) { float v = X[(size_t)row * DIN + c]; a += v * v; }
    for (int o = 16; o; o >>= 1) a += __shfl_xor_sync(0xffffffffu, a, o);
    if (lane == 0) g_sq[row] = a;
}

// ---- symmetric dist GEMM: upper-tri 128x128 blocks, mirrored f4 writes ----
__global__ __launch_bounds__(256) void k_aat_dist_sym(const float* __restrict__ A) {
    __shared__ float As[2][16][128];
    __shared__ float Bs[2][16][128];
    int b = blockIdx.x, by = 0;
    while (b >= 32 - by) { b -= 32 - by; ++by; }
    int bx = by + b;
    int row0 = by * 128, col0 = bx * 128;
    int t = threadIdx.x;
    int ty = t >> 4, tx = t & 15;
    int ra = t >> 2, qa = (t & 3) * 4;

    float4 pa0, pa1, pb0, pb1;
    pa0 = *(const float4*)&A[(size_t)(row0 + ra) * DIN + qa];
    pa1 = *(const float4*)&A[(size_t)(row0 + ra + 64) * DIN + qa];
    pb0 = *(const float4*)&A[(size_t)(col0 + ra) * DIN + qa];
    pb1 = *(const float4*)&A[(size_t)(col0 + ra + 64) * DIN + qa];
    As[0][qa + 0][ra] = pa0.x; As[0][qa + 1][ra] = pa0.y; As[0][qa + 2][ra] = pa0.z; As[0][qa + 3][ra] = pa0.w;
    As[0][qa + 0][ra + 64] = pa1.x; As[0][qa + 1][ra + 64] = pa1.y; As[0][qa + 2][ra + 64] = pa1.z; As[0][qa + 3][ra + 64] = pa1.w;
    Bs[0][qa + 0][ra] = pb0.x; Bs[0][qa + 1][ra] = pb0.y; Bs[0][qa + 2][ra] = pb0.z; Bs[0][qa + 3][ra] = pb0.w;
    Bs[0][qa + 0][ra + 64] = pb1.x; Bs[0][qa + 1][ra + 64] = pb1.y; Bs[0][qa + 2][ra + 64] = pb1.z; Bs[0][qa + 3][ra + 64] = pb1.w;
    __syncthreads();

    float acc[8][8];
#pragma unroll
    for (int i = 0; i < 8; i++)
#pragma unroll
        for (int j = 0; j < 8; j++) acc[i][j] = 0.f;

    const int nIt = DIN / 16;
    for (int it = 0; it < nIt; ++it) {
        int k0n = (it + 1) * 16;
        if (it + 1 < nIt) {
            pa0 = *(const float4*)&A[(size_t)(row0 + ra) * DIN + k0n + qa];
            pa1 = *(const float4*)&A[(size_t)(row0 + ra + 64) * DIN + k0n + qa];
            pb0 = *(const float4*)&A[(size_t)(col0 + ra) * DIN + k0n + qa];
            pb1 = *(const float4*)&A[(size_t)(col0 + ra + 64) * DIN + k0n + qa];
        }
        int buf = it & 1;
#pragma unroll
        for (int kk = 0; kk < 16; ++kk) {
            float4 a0 = *(const float4*)&As[buf][kk][ty * 8];
            float4 a1 = *(const float4*)&As[buf][kk][ty * 8 + 4];
            float4 b0 = *(const float4*)&Bs[buf][kk][tx * 8];
            float4 b1 = *(const float4*)&Bs[buf][kk][tx * 8 + 4];
            float ar[8] = {a0.x, a0.y, a0.z, a0.w, a1.x, a1.y, a1.z, a1.w};
            float br[8] = {b0.x, b0.y, b0.z, b0.w, b1.x, b1.y, b1.z, b1.w};
#pragma unroll
            for (int i = 0; i < 8; i++)
#pragma unroll
                for (int j = 0; j < 8; j++) acc[i][j] += ar[i] * br[j];
        }
        if (it + 1 < nIt) {
            int nb = buf ^ 1;
            As[nb][qa + 0][ra] = pa0.x; As[nb][qa + 1][ra] = pa0.y; As[nb][qa + 2][ra] = pa0.z; As[nb][qa + 3][ra] = pa0.w;
            As[nb][qa + 0][ra + 64] = pa1.x; As[nb][qa + 1][ra + 64] = pa1.y; As[nb][qa + 2][ra + 64] = pa1.z; As[nb][qa + 3][ra + 64] = pa1.w;
            Bs[nb][qa + 0][ra] = pb0.x; Bs[nb][qa + 1][ra] = pb0.y; Bs[nb][qa + 2][ra] = pb0.z; Bs[nb][qa + 3][ra] = pb0.w;
            Bs[nb][qa + 0][ra + 64] = pb1.x; Bs[nb][qa + 1][ra + 64] = pb1.y; Bs[nb][qa + 2][ra + 64] = pb1.z; Bs[nb][qa + 3][ra + 64] = pb1.w;
        }
        __syncthreads();
    }

    float si_[8], sj_[8];
#pragma unroll
    for (int i = 0; i < 8; i++) si_[i] = g_sq[row0 + ty * 8 + i];
#pragma unroll
    for (int j = 0; j < 8; j++) sj_[j] = g_sq[col0 + tx * 8 + j];

#pragma unroll
    for (int i = 0; i < 8; i++) {
        int gi = row0 + ty * 8 + i;
        float4 w0, w1;
        w0.x = fabsf(si_[i] + sj_[0] - 2.f * acc[i][0]);
        w0.y = fabsf(si_[i] + sj_[1] - 2.f * acc[i][1]);
        w0.z = fabsf(si_[i] + sj_[2] - 2.f * acc[i][2]);
        w0.w = fabsf(si_[i] + sj_[3] - 2.f * acc[i][3]);
        w1.x = fabsf(si_[i] + sj_[4] - 2.f * acc[i][4]);
        w1.y = fabsf(si_[i] + sj_[5] - 2.f * acc[i][5]);
        w1.z = fabsf(si_[i] + sj_[6] - 2.f * acc[i][6]);
        w1.w = fabsf(si_[i] + sj_[7] - 2.f * acc[i][7]);
        *(float4*)&g_dist[(size_t)gi * NPTS + col0 + tx * 8] = w0;
        *(float4*)&g_dist[(size_t)gi * NPTS + col0 + tx * 8 + 4] = w1;
    }
#pragma unroll
    for (int j = 0; j < 8; j++) {
        int gj = col0 + tx * 8 + j;
        float4 w0, w1;
        w0.x = fabsf(si_[0] + sj_[j] - 2.f * acc[0][j]);
        w0.y = fabsf(si_[1] + sj_[j] - 2.f * acc[1][j]);
        w0.z = fabsf(si_[2] + sj_[j] - 2.f * acc[2][j]);
        w0.w = fabsf(si_[3] + sj_[j] - 2.f * acc[3][j]);
        w1.x = fabsf(si_[4] + sj_[j] - 2.f * acc[4][j]);
        w1.y = fabsf(si_[5] + sj_[j] - 2.f * acc[5][j]);
        w1.z = fabsf(si_[6] + sj_[j] - 2.f * acc[6][j]);
        w1.w = fabsf(si_[7] + sj_[j] - 2.f * acc[7][j]);
        *(float4*)&g_dist[(size_t)gj * NPTS + row0 + ty * 8] = w0;
        *(float4*)&g_dist[(size_t)gj * NPTS + row0 + ty * 8 + 4] = w1;
    }
}

// ---- warp-per-row top-11 + fused degree count ----
__device__ __forceinline__ bool pless(float av, int ai, float bv, int bi) {
    return av < bv || (av == bv && ai < bi);
}

__global__ __launch_bounds__(256) void k_topk_warp() {
    int row = blockIdx.x * 8 + (threadIdx.x >> 5);
    int lane = threadIdx.x & 31;
    const float* drow = &g_dist[(size_t)row * NPTS];
    float lv[KP1]; int li[KP1];
#pragma unroll
    for (int q = 0; q < KP1; q++) { lv[q] = FLT_MAX; li[q] = 0x7fffffff; }
#pragma unroll 4
    for (int s = 0; s < 128; s++) {
        int j = lane + (s << 5);
        float v = drow[j];
        if (pless(v, j, lv[KP1 - 1], li[KP1 - 1])) {
            lv[KP1 - 1] = v; li[KP1 - 1] = j;
#pragma unroll
            for (int q = KP1 - 1; q > 0; q--) {
                if (pless(lv[q], li[q], lv[q - 1], li[q - 1])) {
                    float tv_ = lv[q]; lv[q] = lv[q - 1]; lv[q - 1] = tv_;
                    int ti_ = li[q]; li[q] = li[q - 1]; li[q - 1] = ti_;
                }
            }
        }
    }
    for (int it = 0; it < KP1; ++it) {
        float v = lv[0]; int ix = li[0];
#pragma unroll
        for (int o = 16; o; o >>= 1) {
            float ov = __shfl_xor_sync(0xffffffffu, v, o);
            int oi = __shfl_xor_sync(0xffffffffu, ix, o);
            if (pless(ov, oi, v, ix)) { v = ov; ix = oi; }
        }
        if (li[0] == ix) {   // unique winner lane pops its head
#pragma unroll
            for (int q = 0; q < KP1 - 1; q++) { lv[q] = lv[q + 1]; li[q] = li[q + 1]; }
            lv[KP1 - 1] = FLT_MAX; li[KP1 - 1] = 0x7fffffff;
        }
        if (lane == 0) {
            g_idx[row * KP1 + it] = ix;
            atomicAdd(&g_deg[ix], 1);
        }
    }
}

// parallel scan of deg + dv + cursor + CSR fill, single block
__global__ void k_scanfill() {
    __shared__ int s[1024];
    int t = threadIdx.x;
    int base = t * 4;
    int v0 = g_deg[base], v1 = g_deg[base + 1], v2 = g_deg[base + 2], v3 = g_deg[base + 3];
    int sum = v0 + v1 + v2 + v3;
    s[t] = sum;
    __syncthreads();
    for (int off = 1; off < 1024; off <<= 1) {
        int x = (t >= off) ? s[t - off] : 0;
        __syncthreads();
        s[t] += x;
        __syncthreads();
    }
    int run = s[t] - sum;
    g_roff[base] = run; g_cursor[base] = run; g_dv[base] = rsqrtf((float)v0); run += v0;
    g_roff[base + 1] = run; g_cursor[base + 1] = run; g_dv[base + 1] = rsqrtf((float)v1); run += v1;
    g_roff[base + 2] = run; g_cursor[base + 2] = run; g_dv[base + 2] = rsqrtf((float)v2); run += v2;
    g_roff[base + 3] = run; g_cursor[base + 3] = run; g_dv[base + 3] = rsqrtf((float)v3); run += v3;
    if (t == 1023) g_roff[NPTS] = run;
    __syncthreads();
    for (int p = t; p < NPTS * KP1; p += 1024) {
        int i = g_idx[p];
        int pos = atomicAdd(&g_cursor[i], 1);
        g_redge[pos] = p / KP1;
    }
}

// dedup'd ascending neighbor lists into g_dist region
__global__ void k_nbr() {
    __shared__ unsigned bm[128];
    __shared__ int wsum[4];
    int i = blockIdx.x, t = threadIdx.x;
    bm[t] = 0u;
    __syncthreads();
    int beg = g_roff[i];
    int cnt = (g_roff[i + 1] - beg) * KP1;
    for (int p = t; p < cnt; p += 128) {
        int e = g_redge[beg + p / KP1];
        int m = g_idx[e * KP1 + p % KP1];
        atomicOr(&bm[m >> 5], 1u << (m & 31));
    }
    __syncthreads();
    if (t == 0) bm[i >> 5] &= ~(1u << (i & 31));
    __syncthreads();
    unsigned w = bm[t];
    int pc = __popc(w);
    int lane = t & 31, wid = t >> 5;
    int sc = pc;
    for (int o = 1; o < 32; o <<= 1) {
        int x = __shfl_up_sync(0xffffffffu, sc, o);
        if (lane >= o) sc += x;
    }
    if (lane == 31) wsum[wid] = sc;
    __syncthreads();
    int woff = 0;
    for (int q = 0; q < wid; q++) woff += wsum[q];
    int off = woff + sc - pc;
    int* nbr = (int*)g_dist + (size_t)i * NPTS;
    while (w) {
        int b = __ffs(w) - 1; w &= w - 1;
        nbr[off++] = t * 32 + b;
    }
    if (t == 127) g_ncnt[i] = woff + sc;
}

// ---- 128x64 GEMM, double buffered ----
__device__ __forceinline__ void gemm64_body(const float* __restrict__ A,
                                            const float* __restrict__ B, int ldb,
                                            float* __restrict__ C, int ldc,
                                            int K, int m0, int n0b) {
    __shared__ float As[2][16][128];
    __shared__ float Bs[2][16][64];
    int t = threadIdx.x;
    int ty = t >> 4, tx = t & 15;
    int ra = t >> 1, qa = (t & 1) * 8;
    int kb = t >> 4, cb = (t & 15) * 4;

    float4 pa0, pa1, pb;
    pa0 = *(const float4*)&A[(size_t)(m0 + ra) * K + qa];
    pa1 = *(const float4*)&A[(size_t)(m0 + ra) * K + qa + 4];
    pb = *(const float4*)&B[(size_t)kb * ldb + cb];
    As[0][qa + 0][ra] = pa0.x; As[0][qa + 1][ra] = pa0.y; As[0][qa + 2][ra] = pa0.z; As[0][qa + 3][ra] = pa0.w;
    As[0][qa + 4][ra] = pa1.x; As[0][qa + 5][ra] = pa1.y; As[0][qa + 6][ra] = pa1.z; As[0][qa + 7][ra] = pa1.w;
    *(float4*)&Bs[0][kb][cb] = pb;
    __syncthreads();

    float acc[8][4];
#pragma unroll
    for (int i = 0; i < 8; i++)
#pragma unroll
        for (int j = 0; j < 4; j++) acc[i][j] = 0.f;

    int nIt = K / 16;
    for (int it = 0; it < nIt; ++it) {
        int k0n = (it + 1) * 16;
        if (it + 1 < nIt) {
            pa0 = *(const float4*)&A[(size_t)(m0 + ra) * K + k0n + qa];
            pa1 = *(const float4*)&A[(size_t)(m0 + ra) * K + k0n + qa + 4];
            pb = *(const float4*)&B[(size_t)(k0n + kb) * ldb + cb];
        }
        int buf = it & 1;
#pragma unroll
        for (int kk = 0; kk < 16; ++kk) {
            float4 a0 = *(const float4*)&As[buf][kk][ty * 8];
            float4 a1 = *(const float4*)&As[buf][kk][ty * 8 + 4];
            float4 b0 = *(const float4*)&Bs[buf][kk][tx * 4];
            float ar[8] = {a0.x, a0.y, a0.z, a0.w, a1.x, a1.y, a1.z, a1.w};
            float br[4] = {b0.x, b0.y, b0.z, b0.w};
#pragma unroll
            for (int i = 0; i < 8; i++)
#pragma unroll
                for (int j = 0; j < 4; j++) acc[i][j] += ar[i] * br[j];
        }
        if (it + 1 < nIt) {
            int nb = buf ^ 1;
            As[nb][qa + 0][ra] = pa0.x; As[nb][qa + 1][ra] = pa0.y; As[nb][qa + 2][ra] = pa0.z; As[nb][qa + 3][ra] = pa0.w;
            As[nb][qa + 4][ra] = pa1.x; As[nb][qa + 5][ra] = pa1.y; As[nb][qa + 6][ra] = pa1.z; As[nb][qa + 7][ra] = pa1.w;
            *(float4*)&Bs[nb][kb][cb] = pb;
        }
        __syncthreads();
    }
#pragma unroll
    for (int i = 0; i < 8; i++) {
        float4 w0 = {acc[i][0], acc[i][1], acc[i][2], acc[i][3]};
        *(float4*)&C[(size_t)(m0 + ty * 8 + i) * ldc + n0b + tx * 4] = w0;
    }
}

__global__ __launch_bounds__(256) void k_gemm64(const float* __restrict__ A,
                                                const float* __restrict__ B,
                                                float* __restrict__ C, int K, int Np) {
    gemm64_body(A, B + blockIdx.x * 64, Np, C, Np, K, blockIdx.y * 128, blockIdx.x * 64);
}

// dual-source heads GEMM: by<32 -> A1->C1 else A2->C2; bx = head
__global__ __launch_bounds__(256) void k_gemm64h2(const float* __restrict__ A1,
                                                  const float* __restrict__ A2,
                                                  const float* __restrict__ Wh,
                                                  float* __restrict__ C1,
                                                  float* __restrict__ C2) {
    int half = blockIdx.y >> 5;
    int m0 = (blockIdx.y & 31) * 128;
    int h = blockIdx.x;
    gemm64_body(half ? A2 : A1, Wh + (size_t)h * DHID * 64, 64,
                half ? C2 : C1, DHID, DHID, m0, h * 64);
}

// dual-source shared-B GEMM: by<32 -> A1->C1 else A2->C2; bx = col tile
__global__ __launch_bounds__(256) void k_gemm64d(const float* __restrict__ A1,
                                                 const float* __restrict__ A2,
                                                 const float* __restrict__ B,
                                                 float* __restrict__ C1,
                                                 float* __restrict__ C2) {
    int half = blockIdx.y >> 5;
    int m0 = (blockIdx.y & 31) * 128;
    gemm64_body(half ? A2 : A1, B + blockIdx.x * 64, DHID,
                half ? C2 : C1, DHID, DHID, m0, blockIdx.x * 64);
}

// ---- hypergraph gathers (vectorized, norm fused into edges) ----
__global__ void k_gather_edges() {
    int e = blockIdx.x * 4 + (threadIdx.x >> 5);
    int lane = threadIdx.x & 31;
    float4 a0 = {0, 0, 0, 0}, a1 = {0, 0, 0, 0};
    for (int k = 0; k < KP1; k++) {
        int i = g_idx[e * KP1 + k];
        float w = g_dv[i];
        const float4* r = (const float4*)&g_XT[(size_t)i * DHID];
        float4 x0 = r[lane], x1 = r[lane + 32];
        a0.x += w * x0.x; a0.y += w * x0.y; a0.z += w * x0.z; a0.w += w * x0.w;
        a1.x += w * x1.x; a1.y += w * x1.y; a1.z += w * x1.z; a1.w += w * x1.w;
    }
    a0.x *= DE_C; a0.y *= DE_C; a0.z *= DE_C; a0.w *= DE_C;
    a1.x *= DE_C; a1.y *= DE_C; a1.z *= DE_C; a1.w *= DE_C;
    float4* o = (float4*)&g_Xe[(size_t)e * DHID];
    o[lane] = a0; o[lane + 32] = a1;
    // fused row norm
    float nq = a0.x * a0.x + a0.y * a0.y + a0.z * a0.z + a0.w * a0.w
             + a1.x * a1.x + a1.y * a1.y + a1.z * a1.z + a1.w * a1.w;
    for (int of = 16; of; of >>= 1) nq += __shfl_xor_sync(0xffffffffu, nq, of);
    if (lane == 0) g_nrm[e] = sqrtf(nq);
}

__global__ void k_gather_nodes() {
    int i = blockIdx.x * 4 + (threadIdx.x >> 5);
    int lane = threadIdx.x & 31;
    int beg = g_roff[i], end = g_roff[i + 1];
    float4 a0 = {0, 0, 0, 0}, a1 = {0, 0, 0, 0};
    for (int k = beg; k < end; k++) {
        const float4* r = (const float4*)&g_Xe[(size_t)g_redge[k] * DHID];
        float4 x0 = r[lane], x1 = r[lane + 32];
        a0.x += x0.x; a0.y += x0.y; a0.z += x0.z; a0.w += x0.w;
        a1.x += x1.x; a1.y += x1.y; a1.z += x1.z; a1.w += x1.w;
    }
    float s = g_dv[i] * DE_C;
    a0.x *= s; a0.y *= s; a0.z *= s; a0.w *= s;
    a1.x *= s; a1.y *= s; a1.z *= s; a1.w *= s;
    float4* o = (float4*)&g_E[(size_t)i * DHID];
    o[lane] = a0; o[lane + 32] = a1;
}

__global__ void k_rownorm(const float* __restrict__ Xf) {
    int row = blockIdx.x * 4 + (threadIdx.x >> 5);
    int lane = threadIdx.x & 31;
    const float4* r = (const float4*)&Xf[(size_t)row * DHID];
    float4 x0 = r[lane], x1 = r[lane + 32];
    float a = x0.x * x0.x + x0.y * x0.y + x0.z * x0.z + x0.w * x0.w
            + x1.x * x1.x + x1.y * x1.y + x1.z * x1.z + x1.w * x1.w;
    for (int o = 16; o; o >>= 1) a += __shfl_xor_sync(0xffffffffu, a, o);
    if (lane == 0) g_nrm[row] = sqrtf(a);
}

// density from neighbor lists (deterministic tree sum)
__global__ void k_density(const float* __restrict__ Xf) {
    __shared__ float xs[DHID];
    __shared__ float ps[8];
    int i = blockIdx.x, t = threadIdx.x;
    xs[t] = Xf[(size_t)i * DHID + t];
    __syncthreads();
    int lane = t & 31, wp = t >> 5;
    const float4* xs4 = (const float4*)xs;
    float4 x0 = xs4[lane], x1 = xs4[lane + 32];
    const int* nbr = (const int*)g_dist + (size_t)i * NPTS;
    int n = g_ncnt[i];
    float ni = g_nrm[i], part = 0.f;
    for (int e = wp; e < n; e += 8) {
        int j = nbr[e];
        const float4* r = (const float4*)&Xf[(size_t)j * DHID];
        float4 r0 = r[lane], r1 = r[lane + 32];
        float d = x0.x * r0.x + x0.y * r0.y + x0.z * r0.z + x0.w * r0.w
                + x1.x * r1.x + x1.y * r1.y + x1.z * r1.z + x1.w * r1.w;
        for (int o = 16; o; o >>= 1) d += __shfl_xor_sync(0xffffffffu, d, o);
        if (lane == 0) {
            float cs = d / (ni * g_nrm[j]);
            if (cs > SIGMA_C) part += cs;
        }
    }
    if (lane == 0) ps[wp] = part;
    __syncthreads();
    if (t == 0) {
        float a = 0.f;
        for (int q = 0; q < 8; q++) a += ps[q];
        g_rho[i] = a;
    }
}

// rhoe + fused maxima of rho and rhoe
__global__ void k_rhoe(int rslot, int reslot) {
    __shared__ float sm1[8], sm2[8];
    int e = blockIdx.x * 256 + threadIdx.x;
    float r = 0.f;
    for (int k = 0; k < KP1; k++) r += g_rho[g_idx[e * KP1 + k]];
    g_rhoe[e] = r;
    float rr = g_rho[e];
    for (int o = 16; o; o >>= 1) {
        r = fmaxf(r, __shfl_xor_sync(0xffffffffu, r, o));
        rr = fmaxf(rr, __shfl_xor_sync(0xffffffffu, rr, o));
    }
    int t = threadIdx.x;
    if ((t & 31) == 0) { sm1[t >> 5] = rr; sm2[t >> 5] = r; }
    __syncthreads();
    if (t == 0) {
        float m1 = sm1[0], m2 = sm2[0];
        for (int q = 1; q < 8; q++) { m1 = fmaxf(m1, sm1[q]); m2 = fmaxf(m2, sm2[q]); }
        atomicMax(&g_smax[rslot], encf(m1));
        atomicMax(&g_smax[reslot], encf(m2));
    }
}

// all-heads s/t matvec (D=64) + fused per-slot max
__global__ void k_svtv4(const float* __restrict__ Ms, const float* __restrict__ Mt,
                        const float* __restrict__ av, int sb) {
    __shared__ float sm[8];
    int w = (blockIdx.x * 256 + threadIdx.x) >> 5;
    int lane = threadIdx.x & 31;
    int row = w & (NPTS - 1);
    int g = w >> 12;
    int h = g & 3, which = g >> 2;
    const float* M = which ? Mt : Ms;
    const float* a = av + (size_t)h * 2 * DHEAD + which * DHEAD;
    const float* r = M + (size_t)row * DHID + h * DHEAD;
    float p = r[lane] * a[lane] + r[lane + 32] * a[lane + 32];
    for (int o = 16; o; o >>= 1) p += __shfl_xor_sync(0xffffffffu, p, o);
    if (lane == 0) {
        (which ? g_tvh : g_svh)[h * NPTS + row] = p;
        sm[(threadIdx.x >> 5)] = p;
    }
    __syncthreads();
    if (threadIdx.x == 0) {
        float m = sm[0];
        for (int q = 1; q < 8; q++) m = fmaxf(m, sm[q]);
        atomicMax(&g_smax[sb + which * 4 + h], encf(m));
    }
}

// final s/t matvec D=256 + fused max
__global__ void k_svtv1(const float* __restrict__ Ms, const float* __restrict__ as,
                        const float* __restrict__ Mt, const float* __restrict__ at, int sb) {
    __shared__ float sm[8];
    int w = (blockIdx.x * 256 + threadIdx.x) >> 5;
    int lane = threadIdx.x & 31;
    int row = w & (NPTS - 1);
    int which = w >> 12;
    const float* M = which ? Mt : Ms;
    const float* a = which ? at : as;
    const float4* r = (const float4*)(M + (size_t)row * DHID);
    const float4* a4 = (const float4*)a;
    float4 r0 = r[lane], r1 = r[lane + 32];
    float4 b0 = a4[lane], b1 = a4[lane + 32];
    float p = r0.x * b0.x + r0.y * b0.y + r0.z * b0.z + r0.w * b0.w
            + r1.x * b1.x + r1.y * b1.y + r1.z * b1.z + r1.w * b1.w;
    for (int o = 16; o; o >>= 1) p += __shfl_xor_sync(0xffffffffu, p, o);
    if (lane == 0) {
        (which ? g_tvh : g_svh)[row] = p;
        sm[(threadIdx.x >> 5)] = p;
    }
    __syncthreads();
    if (threadIdx.x == 0) {
        float m = sm[0];
        for (int q = 1; q < 8; q++) m = fmaxf(m, sm[q]);
        atomicMax(&g_smax[sb + which], encf(m));
    }
}

__device__ __forceinline__ float lrelu(float x) { return x > 0.f ? x : 0.2f * x; }

// attention: grid (1024, nheads); head = blockIdx.y; decodes fused maxima
template <int D>
__global__ void k_att4(const float* __restrict__ rho, int rslot,
                       const float* __restrict__ valb, int ldv,
                       float* __restrict__ outb, int ldo, int hstride, int sb, int nh) {
    int h = blockIdx.y;
    int row = blockIdx.x * 4 + (threadIdx.x >> 5);
    int lane = threadIdx.x & 31;
    const float* sA = g_svh + h * NPTS;
    const float* tA = g_tvh + h * NPTS;
    float smx = decf(g_smax[sb + h]);
    float tmx = decf(g_smax[sb + nh + h]);
    float ax_max = lrelu(smx + tmx);
    float rt = rho[row] / decf(g_smax[rslot]) * ax_max;
    float si = sA[row];
    int beg = g_roff[row], end = g_roff[row + 1];
    int deg = end - beg;
    const float* val = valb + h * hstride;
    float* out = outb + h * hstride;
    const int CH = D / 32;
    float acc[CH];
#pragma unroll
    for (int j = 0; j < CH; j++) acc[j] = 0.f;
    float iz;
    if (deg <= 32) {
        int mye = (lane < deg) ? g_redge[beg + lane] : 0;
        float st = (lane < deg) ? (lrelu(si + tA[mye]) + rt) : -FLT_MAX;
        float m = st;
        for (int o = 16; o; o >>= 1) m = fmaxf(m, __shfl_xor_sync(0xffffffffu, m, o));
        float myw = (lane < deg) ? expf(st - m) : 0.f;
        float Z = myw;
        for (int o = 16; o; o >>= 1) Z += __shfl_xor_sync(0xffffffffu, Z, o);
        for (int k = 0; k < deg; k++) {
            int e = __shfl_sync(0xffffffffu, mye, k);
            float wt = __shfl_sync(0xffffffffu, myw, k);
            const float* v = &val[(size_t)e * ldv];
#pragma unroll
            for (int j = 0; j < CH; j++) acc[j] += wt * v[lane + j * 32];
        }
        iz = 1.f / Z;
    } else {
        float m = -FLT_MAX;
        for (int k = beg + lane; k < end; k += 32)
            m = fmaxf(m, lrelu(si + tA[g_redge[k]]) + rt);
        for (int o = 16; o; o >>= 1) m = fmaxf(m, __shfl_xor_sync(0xffffffffu, m, o));
        float Z = 0.f;
        for (int k = beg + lane; k < end; k += 32)
            Z += expf(lrelu(si + tA[g_redge[k]]) + rt - m);
        for (int o = 16; o; o >>= 1) Z += __shfl_xor_sync(0xffffffffu, Z, o);
        for (int k = beg; k < end; k++) {
            int e = g_redge[k];
            float wt = expf(lrelu(si + tA[e]) + rt - m);
            const float* v = &val[(size_t)e * ldv];
#pragma unroll
            for (int j = 0; j < CH; j++) acc[j] += wt * v[lane + j * 32];
        }
        iz = 1.f / Z;
    }
#pragma unroll
    for (int j = 0; j < CH; j++) {
        float x = acc[j] * iz;
        out[(size_t)row * ldo + lane + j * 32] = x > 0.f ? x : expm1f(x);
    }
}

// ---------------- host orchestration ----------------
extern "C" void kernel_launch(void* const* d_in, const int* in_sizes, int n_in,
                              void* d_out, int out_size) {
    const float* X     = (const float*)d_in[0];
    const float* theta = (const float*)d_in[1];
    const float* Wh    = (const float*)d_in[2];
    const float* axh   = (const float*)d_in[3];
    const float* aeh   = (const float*)d_in[4];
    const float* W2    = (const float*)d_in[5];
    const float* ax2   = (const float*)d_in[6];
    const float* ae2   = (const float*)d_in[7];
    float* out = (float*)d_out;
    (void)in_sizes; (void)n_in; (void)out_size;

    void* vp;
    cudaGetSymbolAddress(&vp, g_XT);   float* XT   = (float*)vp;
    cudaGetSymbolAddress(&vp, g_Xe);   float* Xe   = (float*)vp;
    cudaGetSymbolAddress(&vp, g_E);    float* E    = (float*)vp;
    cudaGetSymbolAddress(&vp, g_rho);  float* rho  = (float*)vp;
    cudaGetSymbolAddress(&vp, g_rhoe); float* rhoe = (float*)vp;
    cudaGetSymbolAddress(&vp, g_P);    float* P    = (float*)vp;
    cudaGetSymbolAddress(&vp, g_Q);    float* Q    = (float*)vp;
    cudaGetSymbolAddress(&vp, g_Enew); float* Enew = (float*)vp;
    cudaGetSymbolAddress(&vp, g_Xcat); float* Xcat = (float*)vp;

    // launches 1-3 independent of dist; dist = launch #4 (profiled slot)
    k_zeroinit<<<1, 1024>>>();
    k_rowsq<<<NPTS / 4, 128>>>(X);
    k_gemm64<<<dim3(4, 32), 256>>>(X, theta, XT, DIN, DHID);
    k_aat_dist_sym<<<528, 256>>>(X);

    k_topk_warp<<<512, 256>>>();
    k_scanfill<<<1, 1024>>>();
    k_gather_edges<<<NPTS / 4, 128>>>();
    k_gather_nodes<<<NPTS / 4, 128>>>();
    k_nbr<<<NPTS, 128>>>();

    // densities (stage 1)
    k_density<<<NPTS, 256>>>(Xe);
    k_rhoe<<<16, 256>>>(20, 21);

    // all-head projections (one launch)
    k_gemm64h2<<<dim3(4, 64), 256>>>(Xe, E, Wh, P, Q);

    // attention pass 1
    k_svtv4<<<4096, 256>>>(P, Q, axh, 0);
    k_att4<DHEAD><<<dim3(NPTS / 4, MH), 128>>>(rho, 20, P, DHID, Enew, DHID, DHEAD, 0, 4);

    // attention pass 2
    k_svtv4<<<4096, 256>>>(Q, P, aeh, 8);
    k_att4<DHEAD><<<dim3(NPTS / 4, MH), 128>>>(rhoe, 21, Enew, DHID, Xcat, DHID, DHEAD, 8, 4);

    // final DA-HGAN layer
    k_rownorm<<<NPTS / 4, 128>>>(Xcat);
    k_density<<<NPTS, 256>>>(Xcat);
    k_rhoe<<<16, 256>>>(22, 23);

    k_gemm64d<<<dim3(4, 64), 256>>>(Xcat, E, W2, P, Q);

    k_svtv1<<<1024, 256>>>(P, ax2, Q, ax2 + DHID, 16);
    k_att4<DHID><<<dim3(NPTS / 4, 1), 128>>>(rho, 22, P, DHID, Enew, DHID, 0, 16, 1);

    k_svtv1<<<1024, 256>>>(Q, ae2, P, ae2 + DHID, 18);
    k_att4<DHID><<<dim3(NPTS / 4, 1), 128>>>(rhoe, 23, Enew, DHID, out, DHID, 0, 18, 1);
}

// round 6
// speedup vs baseline: 1.8448x; 1.1728x over previous
#include <cuda_runtime.h>
#include <math.h>
#include <float.h>

// ---------------- problem constants ----------------
#define NPTS  4096
#define DIN   784
#define DHID  256
#define MH    4
#define DHEAD 64
#define KP1   11
#define SIGMA_C 0.1f
#define DE_C  0.30151134457776363f   // 1/sqrt(11)

// ---------------- device scratch ----------------
__device__ float g_dist[(size_t)NPTS * NPTS];  // 64MB; after topk reused as int nbr[4096][4096]
__device__ float g_sq[NPTS];
__device__ int   g_idx[NPTS * KP1];
__device__ int   g_deg[NPTS];
__device__ float g_dv[NPTS];
__device__ int   g_roff[NPTS + 1];
__device__ int   g_cursor[NPTS];
__device__ int   g_redge[NPTS * KP1];
__device__ int   g_ncnt[NPTS];
__device__ float g_XT[NPTS * DHID];
__device__ float g_Xe[NPTS * DHID];
__device__ float g_E[NPTS * DHID];
__device__ float g_nrm[NPTS];
__device__ float g_rho[NPTS];
__device__ float g_rhoe[NPTS];
__device__ float g_P[NPTS * DHID];
__device__ float g_Q[NPTS * DHID];
__device__ float g_svh[MH * NPTS];
__device__ float g_tvh[MH * NPTS];
__device__ float g_Enew[NPTS * DHID];
__device__ float g_Xcat[NPTS * DHID];
__device__ unsigned g_smax[32];   // encoded float maxima

// slots: [0..3] att1 s/head  [4..7] att1 t/head
//        [8..11] att2 s/head [12..15] att2 t/head
//        [16,17] fin1 s,t    [18,19] fin2 s,t
//        [20] rho1  [21] rhoe1  [22] rho2  [23] rhoe2

__device__ __forceinline__ unsigned encf(float f) {
    unsigned u = __float_as_uint(f);
    return (u & 0x80000000u) ? ~u : (u | 0x80000000u);
}
__device__ __forceinline__ float decf(unsigned u) {
    return __uint_as_float((u & 0x80000000u) ? (u & 0x7fffffffu) : ~u);
}

// ---------------- init ----------------
__global__ void k_zeroinit() {
    int t = threadIdx.x;
    for (int i = t; i < NPTS; i += 1024) g_deg[i] = 0;
    if (t < 32) g_smax[t] = 0u;
}

__global__ void k_rowsq(const float* __restrict__ X) {
    int row = blockIdx.x * 4 + (threadIdx.x >> 5);
    int lane = threadIdx.x & 31;
    const float4* r = (const float4*)&X[(size_t)row * DIN];
    float a = 0.f;
    for (int c = lane; c < DIN / 4; c += 32) {
        float4 v = r[c];
        a += v.x * v.x + v.y * v.y + v.z * v.z + v.w * v.w;
    }
    for (int o = 16; o; o >>= 1) a += __shfl_xor_sync(0xffffffffu, a, o);
    if (lane == 0) g_sq[row] = a;
}

// ---- symmetric dist GEMM: upper-tri 128x128 blocks, mirrored f4 writes ----
__global__ __launch_bounds__(256) void k_aat_dist_sym(const float* __restrict__ A) {
    __shared__ float As[2][16][128];
    __shared__ float Bs[2][16][128];
    int b = blockIdx.x, by = 0;
    while (b >= 32 - by) { b -= 32 - by; ++by; }
    int bx = by + b;
    int row0 = by * 128, col0 = bx * 128;
    int t = threadIdx.x;
    int ty = t >> 4, tx = t & 15;
    int ra = t >> 2, qa = (t & 3) * 4;

    float4 pa0, pa1, pb0, pb1;
    pa0 = *(const float4*)&A[(size_t)(row0 + ra) * DIN + qa];
    pa1 = *(const float4*)&A[(size_t)(row0 + ra + 64) * DIN + qa];
    pb0 = *(const float4*)&A[(size_t)(col0 + ra) * DIN + qa];
    pb1 = *(const float4*)&A[(size_t)(col0 + ra + 64) * DIN + qa];
    As[0][qa + 0][ra] = pa0.x; As[0][qa + 1][ra] = pa0.y; As[0][qa + 2][ra] = pa0.z; As[0][qa + 3][ra] = pa0.w;
    As[0][qa + 0][ra + 64] = pa1.x; As[0][qa + 1][ra + 64] = pa1.y; As[0][qa + 2][ra + 64] = pa1.z; As[0][qa + 3][ra + 64] = pa1.w;
    Bs[0][qa + 0][ra] = pb0.x; Bs[0][qa + 1][ra] = pb0.y; Bs[0][qa + 2][ra] = pb0.z; Bs[0][qa + 3][ra] = pb0.w;
    Bs[0][qa + 0][ra + 64] = pb1.x; Bs[0][qa + 1][ra + 64] = pb1.y; Bs[0][qa + 2][ra + 64] = pb1.z; Bs[0][qa + 3][ra + 64] = pb1.w;
    __syncthreads();

    float acc[8][8];
#pragma unroll
    for (int i = 0; i < 8; i++)
#pragma unroll
        for (int j = 0; j < 8; j++) acc[i][j] = 0.f;

    const int nIt = DIN / 16;
    for (int it = 0; it < nIt; ++it) {
        int k0n = (it + 1) * 16;
        if (it + 1 < nIt) {
            pa0 = *(const float4*)&A[(size_t)(row0 + ra) * DIN + k0n + qa];
            pa1 = *(const float4*)&A[(size_t)(row0 + ra + 64) * DIN + k0n + qa];
            pb0 = *(const float4*)&A[(size_t)(col0 + ra) * DIN + k0n + qa];
            pb1 = *(const float4*)&A[(size_t)(col0 + ra + 64) * DIN + k0n + qa];
        }
        int buf = it & 1;
#pragma unroll
        for (int kk = 0; kk < 16; ++kk) {
            float4 a0 = *(const float4*)&As[buf][kk][ty * 8];
            float4 a1 = *(const float4*)&As[buf][kk][ty * 8 + 4];
            float4 b0 = *(const float4*)&Bs[buf][kk][tx * 8];
            float4 b1 = *(const float4*)&Bs[buf][kk][tx * 8 + 4];
            float ar[8] = {a0.x, a0.y, a0.z, a0.w, a1.x, a1.y, a1.z, a1.w};
            float br[8] = {b0.x, b0.y, b0.z, b0.w, b1.x, b1.y, b1.z, b1.w};
#pragma unroll
            for (int i = 0; i < 8; i++)
#pragma unroll
                for (int j = 0; j < 8; j++) acc[i][j] += ar[i] * br[j];
        }
        if (it + 1 < nIt) {
            int nb = buf ^ 1;
            As[nb][qa + 0][ra] = pa0.x; As[nb][qa + 1][ra] = pa0.y; As[nb][qa + 2][ra] = pa0.z; As[nb][qa + 3][ra] = pa0.w;
            As[nb][qa + 0][ra + 64] = pa1.x; As[nb][qa + 1][ra + 64] = pa1.y; As[nb][qa + 2][ra + 64] = pa1.z; As[nb][qa + 3][ra + 64] = pa1.w;
            Bs[nb][qa + 0][ra] = pb0.x; Bs[nb][qa + 1][ra] = pb0.y; Bs[nb][qa + 2][ra] = pb0.z; Bs[nb][qa + 3][ra] = pb0.w;
            Bs[nb][qa + 0][ra + 64] = pb1.x; Bs[nb][qa + 1][ra + 64] = pb1.y; Bs[nb][qa + 2][ra + 64] = pb1.z; Bs[nb][qa + 3][ra + 64] = pb1.w;
        }
        __syncthreads();
    }

    float si_[8], sj_[8];
#pragma unroll
    for (int i = 0; i < 8; i++) si_[i] = g_sq[row0 + ty * 8 + i];
#pragma unroll
    for (int j = 0; j < 8; j++) sj_[j] = g_sq[col0 + tx * 8 + j];

#pragma unroll
    for (int i = 0; i < 8; i++) {
        int gi = row0 + ty * 8 + i;
        float4 w0, w1;
        w0.x = fabsf(si_[i] + sj_[0] - 2.f * acc[i][0]);
        w0.y = fabsf(si_[i] + sj_[1] - 2.f * acc[i][1]);
        w0.z = fabsf(si_[i] + sj_[2] - 2.f * acc[i][2]);
        w0.w = fabsf(si_[i] + sj_[3] - 2.f * acc[i][3]);
        w1.x = fabsf(si_[i] + sj_[4] - 2.f * acc[i][4]);
        w1.y = fabsf(si_[i] + sj_[5] - 2.f * acc[i][5]);
        w1.z = fabsf(si_[i] + sj_[6] - 2.f * acc[i][6]);
        w1.w = fabsf(si_[i] + sj_[7] - 2.f * acc[i][7]);
        *(float4*)&g_dist[(size_t)gi * NPTS + col0 + tx * 8] = w0;
        *(float4*)&g_dist[(size_t)gi * NPTS + col0 + tx * 8 + 4] = w1;
    }
#pragma unroll
    for (int j = 0; j < 8; j++) {
        int gj = col0 + tx * 8 + j;
        float4 w0, w1;
        w0.x = fabsf(si_[0] + sj_[j] - 2.f * acc[0][j]);
        w0.y = fabsf(si_[1] + sj_[j] - 2.f * acc[1][j]);
        w0.z = fabsf(si_[2] + sj_[j] - 2.f * acc[2][j]);
        w0.w = fabsf(si_[3] + sj_[j] - 2.f * acc[3][j]);
        w1.x = fabsf(si_[4] + sj_[j] - 2.f * acc[4][j]);
        w1.y = fabsf(si_[5] + sj_[j] - 2.f * acc[5][j]);
        w1.z = fabsf(si_[6] + sj_[j] - 2.f * acc[6][j]);
        w1.w = fabsf(si_[7] + sj_[j] - 2.f * acc[7][j]);
        *(float4*)&g_dist[(size_t)gj * NPTS + row0 + ty * 8] = w0;
        *(float4*)&g_dist[(size_t)gj * NPTS + row0 + ty * 8 + 4] = w1;
    }
}

// ---- warp-per-row top-11 (float4 reads) + fused degree count ----
__device__ __forceinline__ bool pless(float av, int ai, float bv, int bi) {
    return av < bv || (av == bv && ai < bi);
}

__global__ __launch_bounds__(256) void k_topk_warp() {
    int row = blockIdx.x * 8 + (threadIdx.x >> 5);
    int lane = threadIdx.x & 31;
    const float4* drow = (const float4*)&g_dist[(size_t)row * NPTS];
    float lv[KP1]; int li[KP1];
#pragma unroll
    for (int q = 0; q < KP1; q++) { lv[q] = FLT_MAX; li[q] = 0x7fffffff; }
#pragma unroll 2
    for (int s = 0; s < 32; s++) {
        int p4 = s * 32 + lane;
        float4 v4 = drow[p4];
        float vv[4] = {v4.x, v4.y, v4.z, v4.w};
        int jb = p4 * 4;
#pragma unroll
        for (int c = 0; c < 4; c++) {
            float v = vv[c]; int j = jb + c;
            if (pless(v, j, lv[KP1 - 1], li[KP1 - 1])) {
                lv[KP1 - 1] = v; li[KP1 - 1] = j;
#pragma unroll
                for (int q = KP1 - 1; q > 0; q--) {
                    if (pless(lv[q], li[q], lv[q - 1], li[q - 1])) {
                        float tv_ = lv[q]; lv[q] = lv[q - 1]; lv[q - 1] = tv_;
                        int ti_ = li[q]; li[q] = li[q - 1]; li[q - 1] = ti_;
                    }
                }
            }
        }
    }
    for (int it = 0; it < KP1; ++it) {
        float v = lv[0]; int ix = li[0];
#pragma unroll
        for (int o = 16; o; o >>= 1) {
            float ov = __shfl_xor_sync(0xffffffffu, v, o);
            int oi = __shfl_xor_sync(0xffffffffu, ix, o);
            if (pless(ov, oi, v, ix)) { v = ov; ix = oi; }
        }
        if (li[0] == ix) {   // unique winner lane pops its head
#pragma unroll
            for (int q = 0; q < KP1 - 1; q++) { lv[q] = lv[q + 1]; li[q] = li[q + 1]; }
            lv[KP1 - 1] = FLT_MAX; li[KP1 - 1] = 0x7fffffff;
        }
        if (lane == 0) {
            g_idx[row * KP1 + it] = ix;
            atomicAdd(&g_deg[ix], 1);
        }
    }
}

// parallel scan of deg + dv + cursor + CSR fill, single block
__global__ void k_scanfill() {
    __shared__ int s[1024];
    int t = threadIdx.x;
    int base = t * 4;
    int v0 = g_deg[base], v1 = g_deg[base + 1], v2 = g_deg[base + 2], v3 = g_deg[base + 3];
    int sum = v0 + v1 + v2 + v3;
    s[t] = sum;
    __syncthreads();
    for (int off = 1; off < 1024; off <<= 1) {
        int x = (t >= off) ? s[t - off] : 0;
        __syncthreads();
        s[t] += x;
        __syncthreads();
    }
    int run = s[t] - sum;
    g_roff[base] = run; g_cursor[base] = run; g_dv[base] = rsqrtf((float)v0); run += v0;
    g_roff[base + 1] = run; g_cursor[base + 1] = run; g_dv[base + 1] = rsqrtf((float)v1); run += v1;
    g_roff[base + 2] = run; g_cursor[base + 2] = run; g_dv[base + 2] = rsqrtf((float)v2); run += v2;
    g_roff[base + 3] = run; g_cursor[base + 3] = run; g_dv[base + 3] = rsqrtf((float)v3); run += v3;
    if (t == 1023) g_roff[NPTS] = run;
    __syncthreads();
    for (int p = t; p < NPTS * KP1; p += 1024) {
        int i = g_idx[p];
        int pos = atomicAdd(&g_cursor[i], 1);
        g_redge[pos] = p / KP1;
    }
}

// dedup'd ascending neighbor lists into g_dist region
__global__ void k_nbr() {
    __shared__ unsigned bm[128];
    __shared__ int wsum[4];
    int i = blockIdx.x, t = threadIdx.x;
    bm[t] = 0u;
    __syncthreads();
    int beg = g_roff[i];
    int cnt = (g_roff[i + 1] - beg) * KP1;
    for (int p = t; p < cnt; p += 128) {
        int e = g_redge[beg + p / KP1];
        int m = g_idx[e * KP1 + p % KP1];
        atomicOr(&bm[m >> 5], 1u << (m & 31));
    }
    __syncthreads();
    if (t == 0) bm[i >> 5] &= ~(1u << (i & 31));
    __syncthreads();
    unsigned w = bm[t];
    int pc = __popc(w);
    int lane = t & 31, wid = t >> 5;
    int sc = pc;
    for (int o = 1; o < 32; o <<= 1) {
        int x = __shfl_up_sync(0xffffffffu, sc, o);
        if (lane >= o) sc += x;
    }
    if (lane == 31) wsum[wid] = sc;
    __syncthreads();
    int woff = 0;
    for (int q = 0; q < wid; q++) woff += wsum[q];
    int off = woff + sc - pc;
    int* nbr = (int*)g_dist + (size_t)i * NPTS;
    while (w) {
        int b = __ffs(w) - 1; w &= w - 1;
        nbr[off++] = t * 32 + b;
    }
    if (t == 127) g_ncnt[i] = woff + sc;
}

// ---- 128x64 GEMM, double buffered ----
__device__ __forceinline__ void gemm64_body(const float* __restrict__ A,
                                            const float* __restrict__ B, int ldb,
                                            float* __restrict__ C, int ldc,
                                            int K, int m0, int n0b) {
    __shared__ float As[2][16][128];
    __shared__ float Bs[2][16][64];
    int t = threadIdx.x;
    int ty = t >> 4, tx = t & 15;
    int ra = t >> 1, qa = (t & 1) * 8;
    int kb = t >> 4, cb = (t & 15) * 4;

    float4 pa0, pa1, pb;
    pa0 = *(const float4*)&A[(size_t)(m0 + ra) * K + qa];
    pa1 = *(const float4*)&A[(size_t)(m0 + ra) * K + qa + 4];
    pb = *(const float4*)&B[(size_t)kb * ldb + cb];
    As[0][qa + 0][ra] = pa0.x; As[0][qa + 1][ra] = pa0.y; As[0][qa + 2][ra] = pa0.z; As[0][qa + 3][ra] = pa0.w;
    As[0][qa + 4][ra] = pa1.x; As[0][qa + 5][ra] = pa1.y; As[0][qa + 6][ra] = pa1.z; As[0][qa + 7][ra] = pa1.w;
    *(float4*)&Bs[0][kb][cb] = pb;
    __syncthreads();

    float acc[8][4];
#pragma unroll
    for (int i = 0; i < 8; i++)
#pragma unroll
        for (int j = 0; j < 4; j++) acc[i][j] = 0.f;

    int nIt = K / 16;
    for (int it = 0; it < nIt; ++it) {
        int k0n = (it + 1) * 16;
        if (it + 1 < nIt) {
            pa0 = *(const float4*)&A[(size_t)(m0 + ra) * K + k0n + qa];
            pa1 = *(const float4*)&A[(size_t)(m0 + ra) * K + k0n + qa + 4];
            pb = *(const float4*)&B[(size_t)(k0n + kb) * ldb + cb];
        }
        int buf = it & 1;
#pragma unroll
        for (int kk = 0; kk < 16; ++kk) {
            float4 a0 = *(const float4*)&As[buf][kk][ty * 8];
            float4 a1 = *(const float4*)&As[buf][kk][ty * 8 + 4];
            float4 b0 = *(const float4*)&Bs[buf][kk][tx * 4];
            float ar[8] = {a0.x, a0.y, a0.z, a0.w, a1.x, a1.y, a1.z, a1.w};
            float br[4] = {b0.x, b0.y, b0.z, b0.w};
#pragma unroll
            for (int i = 0; i < 8; i++)
#pragma unroll
                for (int j = 0; j < 4; j++) acc[i][j] += ar[i] * br[j];
        }
        if (it + 1 < nIt) {
            int nb = buf ^ 1;
            As[nb][qa + 0][ra] = pa0.x; As[nb][qa + 1][ra] = pa0.y; As[nb][qa + 2][ra] = pa0.z; As[nb][qa + 3][ra] = pa0.w;
            As[nb][qa + 4][ra] = pa1.x; As[nb][qa + 5][ra] = pa1.y; As[nb][qa + 6][ra] = pa1.z; As[nb][qa + 7][ra] = pa1.w;
            *(float4*)&Bs[nb][kb][cb] = pb;
        }
        __syncthreads();
    }
#pragma unroll
    for (int i = 0; i < 8; i++) {
        float4 w0 = {acc[i][0], acc[i][1], acc[i][2], acc[i][3]};
        *(float4*)&C[(size_t)(m0 + ty * 8 + i) * ldc + n0b + tx * 4] = w0;
    }
}

__global__ __launch_bounds__(256) void k_gemm64(const float* __restrict__ A,
                                                const float* __restrict__ B,
                                                float* __restrict__ C, int K, int Np) {
    gemm64_body(A, B + blockIdx.x * 64, Np, C, Np, K, blockIdx.y * 128, blockIdx.x * 64);
}

__global__ __launch_bounds__(256) void k_gemm64h2(const float* __restrict__ A1,
                                                  const float* __restrict__ A2,
                                                  const float* __restrict__ Wh,
                                                  float* __restrict__ C1,
                                                  float* __restrict__ C2) {
    int half = blockIdx.y >> 5;
    int m0 = (blockIdx.y & 31) * 128;
    int h = blockIdx.x;
    gemm64_body(half ? A2 : A1, Wh + (size_t)h * DHID * 64, 64,
                half ? C2 : C1, DHID, DHID, m0, h * 64);
}

__global__ __launch_bounds__(256) void k_gemm64d(const float* __restrict__ A1,
                                                 const float* __restrict__ A2,
                                                 const float* __restrict__ B,
                                                 float* __restrict__ C1,
                                                 float* __restrict__ C2) {
    int half = blockIdx.y >> 5;
    int m0 = (blockIdx.y & 31) * 128;
    gemm64_body(half ? A2 : A1, B + blockIdx.x * 64, DHID,
                half ? C2 : C1, DHID, DHID, m0, blockIdx.x * 64);
}

// ---- hypergraph gathers (vectorized, norm fused into edges) ----
__global__ void k_gather_edges() {
    int e = blockIdx.x * 4 + (threadIdx.x >> 5);
    int lane = threadIdx.x & 31;
    float4 a0 = {0, 0, 0, 0}, a1 = {0, 0, 0, 0};
    for (int k = 0; k < KP1; k++) {
        int i = g_idx[e * KP1 + k];
        float w = g_dv[i];
        const float4* r = (const float4*)&g_XT[(size_t)i * DHID];
        float4 x0 = r[lane], x1 = r[lane + 32];
        a0.x += w * x0.x; a0.y += w * x0.y; a0.z += w * x0.z; a0.w += w * x0.w;
        a1.x += w * x1.x; a1.y += w * x1.y; a1.z += w * x1.z; a1.w += w * x1.w;
    }
    a0.x *= DE_C; a0.y *= DE_C; a0.z *= DE_C; a0.w *= DE_C;
    a1.x *= DE_C; a1.y *= DE_C; a1.z *= DE_C; a1.w *= DE_C;
    float4* o = (float4*)&g_Xe[(size_t)e * DHID];
    o[lane] = a0; o[lane + 32] = a1;
    float nq = a0.x * a0.x + a0.y * a0.y + a0.z * a0.z + a0.w * a0.w
             + a1.x * a1.x + a1.y * a1.y + a1.z * a1.z + a1.w * a1.w;
    for (int of = 16; of; of >>= 1) nq += __shfl_xor_sync(0xffffffffu, nq, of);
    if (lane == 0) g_nrm[e] = sqrtf(nq);
}

__global__ void k_gather_nodes() {
    int i = blockIdx.x * 4 + (threadIdx.x >> 5);
    int lane = threadIdx.x & 31;
    int beg = g_roff[i], end = g_roff[i + 1];
    float4 a0 = {0, 0, 0, 0}, a1 = {0, 0, 0, 0};
    for (int k = beg; k < end; k++) {
        const float4* r = (const float4*)&g_Xe[(size_t)g_redge[k] * DHID];
        float4 x0 = r[lane], x1 = r[lane + 32];
        a0.x += x0.x; a0.y += x0.y; a0.z += x0.z; a0.w += x0.w;
        a1.x += x1.x; a1.y += x1.y; a1.z += x1.z; a1.w += x1.w;
    }
    float s = g_dv[i] * DE_C;
    a0.x *= s; a0.y *= s; a0.z *= s; a0.w *= s;
    a1.x *= s; a1.y *= s; a1.z *= s; a1.w *= s;
    float4* o = (float4*)&g_E[(size_t)i * DHID];
    o[lane] = a0; o[lane + 32] = a1;
}

__global__ void k_rownorm(const float* __restrict__ Xf) {
    int row = blockIdx.x * 4 + (threadIdx.x >> 5);
    int lane = threadIdx.x & 31;
    const float4* r = (const float4*)&Xf[(size_t)row * DHID];
    float4 x0 = r[lane], x1 = r[lane + 32];
    float a = x0.x * x0.x + x0.y * x0.y + x0.z * x0.z + x0.w * x0.w
            + x1.x * x1.x + x1.y * x1.y + x1.z * x1.z + x1.w * x1.w;
    for (int o = 16; o; o >>= 1) a += __shfl_xor_sync(0xffffffffu, a, o);
    if (lane == 0) g_nrm[row] = sqrtf(a);
}

// density: 2-way unrolled neighbor dot products (two independent shfl chains)
__global__ void k_density(const float* __restrict__ Xf) {
    __shared__ float xs[DHID];
    __shared__ float ps[8];
    int i = blockIdx.x, t = threadIdx.x;
    xs[t] = Xf[(size_t)i * DHID + t];
    __syncthreads();
    int lane = t & 31, wp = t >> 5;
    const float4* xs4 = (const float4*)xs;
    float4 x0 = xs4[lane], x1 = xs4[lane + 32];
    const int* nbr = (const int*)g_dist + (size_t)i * NPTS;
    int n = g_ncnt[i];
    float ni = g_nrm[i], part = 0.f;
    for (int e0 = wp; e0 < n; e0 += 16) {
        int e1 = e0 + 8;
        bool have2 = (e1 < n);
        int j1 = nbr[e0];
        int j2 = have2 ? nbr[e1] : j1;
        const float4* r1 = (const float4*)&Xf[(size_t)j1 * DHID];
        const float4* r2 = (const float4*)&Xf[(size_t)j2 * DHID];
        float4 a0 = r1[lane], a1 = r1[lane + 32];
        float4 b0 = r2[lane], b1 = r2[lane + 32];
        float d1 = x0.x * a0.x + x0.y * a0.y + x0.z * a0.z + x0.w * a0.w
                 + x1.x * a1.x + x1.y * a1.y + x1.z * a1.z + x1.w * a1.w;
        float d2 = x0.x * b0.x + x0.y * b0.y + x0.z * b0.z + x0.w * b0.w
                 + x1.x * b1.x + x1.y * b1.y + x1.z * b1.z + x1.w * b1.w;
#pragma unroll
        for (int o = 16; o; o >>= 1) {
            d1 += __shfl_xor_sync(0xffffffffu, d1, o);
            d2 += __shfl_xor_sync(0xffffffffu, d2, o);
        }
        if (lane == 0) {
            float c1 = d1 / (ni * g_nrm[j1]);
            if (c1 > SIGMA_C) part += c1;
            if (have2) {
                float c2 = d2 / (ni * g_nrm[j2]);
                if (c2 > SIGMA_C) part += c2;
            }
        }
    }
    if (lane == 0) ps[wp] = part;
    __syncthreads();
    if (t == 0) {
        float a = 0.f;
        for (int q = 0; q < 8; q++) a += ps[q];
        g_rho[i] = a;
    }
}

// rhoe + fused maxima of rho and rhoe
__global__ void k_rhoe(int rslot, int reslot) {
    __shared__ float sm1[8], sm2[8];
    int e = blockIdx.x * 256 + threadIdx.x;
    float r = 0.f;
    for (int k = 0; k < KP1; k++) r += g_rho[g_idx[e * KP1 + k]];
    g_rhoe[e] = r;
    float rr = g_rho[e];
    for (int o = 16; o; o >>= 1) {
        r = fmaxf(r, __shfl_xor_sync(0xffffffffu, r, o));
        rr = fmaxf(rr, __shfl_xor_sync(0xffffffffu, rr, o));
    }
    int t = threadIdx.x;
    if ((t & 31) == 0) { sm1[t >> 5] = rr; sm2[t >> 5] = r; }
    __syncthreads();
    if (t == 0) {
        float m1 = sm1[0], m2 = sm2[0];
        for (int q = 1; q < 8; q++) { m1 = fmaxf(m1, sm1[q]); m2 = fmaxf(m2, sm2[q]); }
        atomicMax(&g_smax[rslot], encf(m1));
        atomicMax(&g_smax[reslot], encf(m2));
    }
}

// all-heads s/t matvec (D=64, float2) + fused per-slot max
__global__ void k_svtv4(const float* __restrict__ Ms, const float* __restrict__ Mt,
                        const float* __restrict__ av, int sb) {
    __shared__ float sm[8];
    int w = (blockIdx.x * 256 + threadIdx.x) >> 5;
    int lane = threadIdx.x & 31;
    int row = w & (NPTS - 1);
    int g = w >> 12;
    int h = g & 3, which = g >> 2;
    const float* M = which ? Mt : Ms;
    const float2* a2 = (const float2*)(av + (size_t)h * 2 * DHEAD + which * DHEAD);
    const float2* r2 = (const float2*)(M + (size_t)row * DHID + h * DHEAD);
    float2 rv = r2[lane], av2 = a2[lane];
    float p = rv.x * av2.x + rv.y * av2.y;
    for (int o = 16; o; o >>= 1) p += __shfl_xor_sync(0xffffffffu, p, o);
    if (lane == 0) {
        (which ? g_tvh : g_svh)[h * NPTS + row] = p;
        sm[(threadIdx.x >> 5)] = p;
    }
    __syncthreads();
    if (threadIdx.x == 0) {
        float m = sm[0];
        for (int q = 1; q < 8; q++) m = fmaxf(m, sm[q]);
        atomicMax(&g_smax[sb + which * 4 + h], encf(m));
    }
}

// final s/t matvec D=256 + fused max
__global__ void k_svtv1(const float* __restrict__ Ms, const float* __restrict__ as,
                        const float* __restrict__ Mt, const float* __restrict__ at, int sb) {
    __shared__ float sm[8];
    int w = (blockIdx.x * 256 + threadIdx.x) >> 5;
    int lane = threadIdx.x & 31;
    int row = w & (NPTS - 1);
    int which = w >> 12;
    const float* M = which ? Mt : Ms;
    const float* a = which ? at : as;
    const float4* r = (const float4*)(M + (size_t)row * DHID);
    const float4* a4 = (const float4*)a;
    float4 r0 = r[lane], r1 = r[lane + 32];
    float4 b0 = a4[lane], b1 = a4[lane + 32];
    float p = r0.x * b0.x + r0.y * b0.y + r0.z * b0.z + r0.w * b0.w
            + r1.x * b1.x + r1.y * b1.y + r1.z * b1.z + r1.w * b1.w;
    for (int o = 16; o; o >>= 1) p += __shfl_xor_sync(0xffffffffu, p, o);
    if (lane == 0) {
        (which ? g_tvh : g_svh)[row] = p;
        sm[(threadIdx.x >> 5)] = p;
    }
    __syncthreads();
    if (threadIdx.x == 0) {
        float m = sm[0];
        for (int q = 1; q < 8; q++) m = fmaxf(m, sm[q]);
        atomicMax(&g_smax[sb + which], encf(m));
    }
}

__device__ __forceinline__ float lrelu(float x) { return x > 0.f ? x : 0.2f * x; }
__device__ __forceinline__ float elu1(float x) { return x > 0.f ? x : expm1f(x); }

// attention: grid (1024, nheads); float2-vectorized value gathers
template <int D>
__global__ void k_att4(const float* __restrict__ rho, int rslot,
                       const float* __restrict__ valb, int ldv,
                       float* __restrict__ outb, int ldo, int hstride, int sb, int nh) {
    int h = blockIdx.y;
    int row = blockIdx.x * 4 + (threadIdx.x >> 5);
    int lane = threadIdx.x & 31;
    const float* sA = g_svh + h * NPTS;
    const float* tA = g_tvh + h * NPTS;
    float smx = decf(g_smax[sb + h]);
    float tmx = decf(g_smax[sb + nh + h]);
    float ax_max = lrelu(smx + tmx);
    float rt = rho[row] / decf(g_smax[rslot]) * ax_max;
    float si = sA[row];
    int beg = g_roff[row], end = g_roff[row + 1];
    int deg = end - beg;
    const float* val = valb + h * hstride;
    float* out = outb + h * hstride;
    const int C2 = D / 64;   // float2 chunks per lane
    float2 acc[C2];
#pragma unroll
    for (int j = 0; j < C2; j++) acc[j] = make_float2(0.f, 0.f);
    float iz;
    if (deg <= 32) {
        int mye = (lane < deg) ? g_redge[beg + lane] : 0;
        float st = (lane < deg) ? (lrelu(si + tA[mye]) + rt) : -FLT_MAX;
        float m = st;
        for (int o = 16; o; o >>= 1) m = fmaxf(m, __shfl_xor_sync(0xffffffffu, m, o));
        float myw = (lane < deg) ? expf(st - m) : 0.f;
        float Z = myw;
        for (int o = 16; o; o >>= 1) Z += __shfl_xor_sync(0xffffffffu, Z, o);
        for (int k = 0; k < deg; k++) {
            int e = __shfl_sync(0xffffffffu, mye, k);
            float wt = __shfl_sync(0xffffffffu, myw, k);
            const float2* v2 = (const float2*)&val[(size_t)e * ldv];
#pragma unroll
            for (int j = 0; j < C2; j++) {
                float2 x = v2[lane + j * 32];
                acc[j].x += wt * x.x; acc[j].y += wt * x.y;
            }
        }
        iz = 1.f / Z;
    } else {
        float m = -FLT_MAX;
        for (int k = beg + lane; k < end; k += 32)
            m = fmaxf(m, lrelu(si + tA[g_redge[k]]) + rt);
        for (int o = 16; o; o >>= 1) m = fmaxf(m, __shfl_xor_sync(0xffffffffu, m, o));
        float Z = 0.f;
        for (int k = beg + lane; k < end; k += 32)
            Z += expf(lrelu(si + tA[g_redge[k]]) + rt - m);
        for (int o = 16; o; o >>= 1) Z += __shfl_xor_sync(0xffffffffu, Z, o);
        for (int k = beg; k < end; k++) {
            int e = g_redge[k];
            float wt = expf(lrelu(si + tA[e]) + rt - m);
            const float2* v2 = (const float2*)&val[(size_t)e * ldv];
#pragma unroll
            for (int j = 0; j < C2; j++) {
                float2 x = v2[lane + j * 32];
                acc[j].x += wt * x.x; acc[j].y += wt * x.y;
            }
        }
        iz = 1.f / Z;
    }
    float2* o2 = (float2*)&out[(size_t)row * ldo];
#pragma unroll
    for (int j = 0; j < C2; j++) {
        float2 r;
        r.x = elu1(acc[j].x * iz);
        r.y = elu1(acc[j].y * iz);
        o2[lane + j * 32] = r;
    }
}

// ---------------- host orchestration ----------------
extern "C" void kernel_launch(void* const* d_in, const int* in_sizes, int n_in,
                              void* d_out, int out_size) {
    const float* X     = (const float*)d_in[0];
    const float* theta = (const float*)d_in[1];
    const float* Wh    = (const float*)d_in[2];
    const float* axh   = (const float*)d_in[3];
    const float* aeh   = (const float*)d_in[4];
    const float* W2    = (const float*)d_in[5];
    const float* ax2   = (const float*)d_in[6];
    const float* ae2   = (const float*)d_in[7];
    float* out = (float*)d_out;
    (void)in_sizes; (void)n_in; (void)out_size;

    void* vp;
    cudaGetSymbolAddress(&vp, g_XT);   float* XT   = (float*)vp;
    cudaGetSymbolAddress(&vp, g_Xe);   float* Xe   = (float*)vp;
    cudaGetSymbolAddress(&vp, g_E);    float* E    = (float*)vp;
    cudaGetSymbolAddress(&vp, g_rho);  float* rho  = (float*)vp;
    cudaGetSymbolAddress(&vp, g_rhoe); float* rhoe = (float*)vp;
    cudaGetSymbolAddress(&vp, g_P);    float* P    = (float*)vp;
    cudaGetSymbolAddress(&vp, g_Q);    float* Q    = (float*)vp;
    cudaGetSymbolAddress(&vp, g_Enew); float* Enew = (float*)vp;
    cudaGetSymbolAddress(&vp, g_Xcat); float* Xcat = (float*)vp;

    // slot layout puts k_topk_warp at launch #4 (the profiled slot)
    k_rowsq<<<NPTS / 4, 128>>>(X);
    k_aat_dist_sym<<<528, 256>>>(X);
    k_zeroinit<<<1, 1024>>>();
    k_topk_warp<<<512, 256>>>();       // profiled

    k_gemm64<<<dim3(4, 32), 256>>>(X, theta, XT, DIN, DHID);
    k_scanfill<<<1, 1024>>>();
    k_gather_edges<<<NPTS / 4, 128>>>();
    k_gather_nodes<<<NPTS / 4, 128>>>();
    k_nbr<<<NPTS, 128>>>();

    // densities (stage 1)
    k_density<<<NPTS, 256>>>(Xe);
    k_rhoe<<<16, 256>>>(20, 21);

    // all-head projections
    k_gemm64h2<<<dim3(4, 64), 256>>>(Xe, E, Wh, P, Q);

    // attention pass 1
    k_svtv4<<<4096, 256>>>(P, Q, axh, 0);
    k_att4<DHEAD><<<dim3(NPTS / 4, MH), 128>>>(rho, 20, P, DHID, Enew, DHID, DHEAD, 0, 4);

    // attention pass 2
    k_svtv4<<<4096, 256>>>(Q, P, aeh, 8);
    k_att4<DHEAD><<<dim3(NPTS / 4, MH), 128>>>(rhoe, 21, Enew, DHID, Xcat, DHID, DHEAD, 8, 4);

    // final DA-HGAN layer
    k_rownorm<<<NPTS / 4, 128>>>(Xcat);
    k_density<<<NPTS, 256>>>(Xcat);
    k_rhoe<<<16, 256>>>(22, 23);

    k_gemm64d<<<dim3(4, 64), 256>>>(Xcat, E, W2, P, Q);

    k_svtv1<<<1024, 256>>>(P, ax2, Q, ax2 + DHID, 16);
    k_att4<DHID><<<dim3(NPTS / 4, 1), 128>>>(rho, 22, P, DHID, Enew, DHID, 0, 16, 1);

    k_svtv1<<<1024, 256>>>(Q, ae2, P, ae2 + DHID, 18);
    k_att4<DHID><<<dim3(NPTS / 4, 1), 128>>>(rhoe, 23, Enew, DHID, out, DHID, 0, 18, 1);
}